// round 6
// baseline (speedup 1.0000x reference)
#include <cuda_runtime.h>
#include <math.h>

#define Bb 8
#define Nn 1024
#define Dd 512
#define Hh 2048
#define Ll 3
#define ROWS (Bb*Nn)   // 8192

// ---------------- device scratch (static, allocation-free) ----------------
__device__ float g_x[ROWS * Dd];
__device__ float g_h[ROWS * Dd];
__device__ float g_attn[(size_t)Bb * Nn * Nn];
__device__ float g_agg[ROWS * Dd];
__device__ float g_hidden[(size_t)ROWS * Hh];
__device__ float g_ff[ROWS * Dd];
__device__ float g_si[ROWS];
__device__ float g_sj[ROWS];

// ---------------- packed f32x2 FMA (sm_100+): 2 fp32 FMAs per issue --------
__device__ __forceinline__ unsigned long long ffma2(unsigned long long a,
                                                    unsigned long long b,
                                                    unsigned long long c)
{
    unsigned long long d;
    asm("fma.rn.f32x2 %0, %1, %2, %3;" : "=l"(d) : "l"(a), "l"(b), "l"(c));
    return d;
}

// ---------------- kernel 1: per-row attention projections si, sj ----------
__global__ void k_scores(const float* __restrict__ x, const float* __restrict__ aw)
{
    int row  = blockIdx.x * 8 + (threadIdx.x >> 5);
    int lane = threadIdx.x & 31;
    const float* xr = x + (size_t)row * Dd;
    float s1 = 0.f, s2 = 0.f;
    #pragma unroll 4
    for (int k = lane; k < Dd; k += 32) {
        float v = xr[k];
        s1 += v * aw[k];
        s2 += v * aw[Dd + k];
    }
    #pragma unroll
    for (int o = 16; o; o >>= 1) {
        s1 += __shfl_xor_sync(0xffffffffu, s1, o);
        s2 += __shfl_xor_sync(0xffffffffu, s2, o);
    }
    if (lane == 0) { g_si[row] = s1; g_sj[row] = s2; }
}

// ---------------- kernel 2: masked LeakyReLU softmax row -------------------
__global__ void k_attn(const int* __restrict__ adj, const float* __restrict__ ab_ptr)
{
    const int row = blockIdx.x;            // b*N + i
    const int b = row >> 10;
    const int i = row & 1023;
    const float ab = ab_ptr[0];
    const int* arow = adj + (size_t)row * Nn;
    const float* sjb = g_sj + b * Nn;
    const float si = g_si[row];

    float sc[Nn / 256];
    float lmax = -3.4e38f;
    #pragma unroll
    for (int t = 0; t < Nn / 256; t++) {
        int j = threadIdx.x + t * 256;
        float s = si + sjb[j] + ab;
        s = (s >= 0.f) ? s : 0.2f * s;
        bool ok = (arow[j] != 0) | (j == i);
        s = ok ? s : -3.4e38f;
        sc[t] = s;
        lmax = fmaxf(lmax, s);
    }
    __shared__ float red[256];
    red[threadIdx.x] = lmax; __syncthreads();
    #pragma unroll
    for (int s = 128; s; s >>= 1) {
        if (threadIdx.x < s) red[threadIdx.x] = fmaxf(red[threadIdx.x], red[threadIdx.x + s]);
        __syncthreads();
    }
    const float m = red[0];
    __syncthreads();

    float lsum = 0.f;
    #pragma unroll
    for (int t = 0; t < Nn / 256; t++) {
        float e = (sc[t] <= -3.0e38f) ? 0.f : expf(sc[t] - m);
        sc[t] = e;
        lsum += e;
    }
    red[threadIdx.x] = lsum; __syncthreads();
    #pragma unroll
    for (int s = 128; s; s >>= 1) {
        if (threadIdx.x < s) red[threadIdx.x] += red[threadIdx.x + s];
        __syncthreads();
    }
    const float inv = 1.f / red[0];
    float* outr = g_attn + (size_t)row * Nn;
    #pragma unroll
    for (int t = 0; t < Nn / 256; t++)
        outr[threadIdx.x + t * 256] = sc[t] * inv;
}

// ---------------- tiled fp32 GEMM with packed f32x2 FMAs -------------------
// C[M,N] = A[M,K] @ B[K,N]  (+bias, +gelu per EPI)
// EPI: 0 = none, 1 = bias + exact gelu, 2 = bias only
template <int EPI>
__global__ void __launch_bounds__(256, 2)
k_gemm(const float* __restrict__ A, const float* __restrict__ Bm,
       float* __restrict__ C, const float* __restrict__ bias,
       int M, int Ncols, int K,
       long long sA, long long sB, long long sC)
{
    constexpr int BM = 128, BN = 128, BK = 8, TM = 8, TN = 8;
    A  += (size_t)blockIdx.z * sA;
    Bm += (size_t)blockIdx.z * sB;
    C  += (size_t)blockIdx.z * sC;

    // A tile stored DUPLICATED: As2[k][2m] == As2[k][2m+1] == A[m][k]
    // so a single LDS.64 yields the packed {a,a} operand for f32x2 FMA.
    __shared__ float As2[BK * BM * 2];   // 8 KB
    __shared__ float Bs[BK * BN];        // 4 KB

    const int tid = threadIdx.x;
    const int cRow = blockIdx.y, cCol = blockIdx.x;

    const int innerRowA = tid >> 1,  innerColA = tid & 1;    // 128x8 via float4
    const int innerRowB = tid >> 5,  innerColB = tid & 31;   // 8x128 via float4
    const int threadRow = tid >> 4,  threadCol = tid & 15;

    A  += (size_t)cRow * BM * K;
    Bm += (size_t)cCol * BN;
    C  += (size_t)cRow * BM * Ncols + (size_t)cCol * BN;

    unsigned long long acc2[TM][TN / 2];
    #pragma unroll
    for (int i = 0; i < TM; i++)
        #pragma unroll
        for (int j = 0; j < TN / 2; j++) acc2[i][j] = 0ULL;

    for (int k0 = 0; k0 < K; k0 += BK) {
        float4 a4 = *(const float4*)(A + (size_t)innerRowA * K + innerColA * 4);
        {
            float2* dst0 = (float2*)&As2[(innerColA * 4 + 0) * (BM * 2) + innerRowA * 2];
            float2* dst1 = (float2*)&As2[(innerColA * 4 + 1) * (BM * 2) + innerRowA * 2];
            float2* dst2 = (float2*)&As2[(innerColA * 4 + 2) * (BM * 2) + innerRowA * 2];
            float2* dst3 = (float2*)&As2[(innerColA * 4 + 3) * (BM * 2) + innerRowA * 2];
            *dst0 = make_float2(a4.x, a4.x);
            *dst1 = make_float2(a4.y, a4.y);
            *dst2 = make_float2(a4.z, a4.z);
            *dst3 = make_float2(a4.w, a4.w);
        }
        *(float4*)(Bs + innerRowB * BN + innerColB * 4) =
            *(const float4*)(Bm + (size_t)innerRowB * Ncols + innerColB * 4);
        __syncthreads();

        A  += BK;
        Bm += (size_t)BK * Ncols;

        #pragma unroll
        for (int k = 0; k < BK; k++) {
            unsigned long long aM[TM], bN[TN / 2];
            #pragma unroll
            for (int i = 0; i < TM; i++)
                aM[i] = *(const unsigned long long*)
                        &As2[k * (BM * 2) + (threadRow * TM + i) * 2];
            #pragma unroll
            for (int j = 0; j < TN / 2; j++)
                bN[j] = *(const unsigned long long*)
                        &Bs[k * BN + threadCol * TN + j * 2];
            #pragma unroll
            for (int i = 0; i < TM; i++)
                #pragma unroll
                for (int j = 0; j < TN / 2; j++)
                    acc2[i][j] = ffma2(aM[i], bN[j], acc2[i][j]);
        }
        __syncthreads();
    }

    const int colBase = cCol * BN + threadCol * TN;
    #pragma unroll
    for (int i = 0; i < TM; i++) {
        float* crow = C + (size_t)(threadRow * TM + i) * Ncols + threadCol * TN;
        #pragma unroll
        for (int j = 0; j < TN; j += 4) {
            float e[4];
            #pragma unroll
            for (int q = 0; q < 4; q++) {
                float2 p = *(float2*)&acc2[i][(j + q) / 2];   // local, no alias issue
                float t = (q & 1) ? p.y : p.x;
                if (EPI >= 1) t += bias[colBase + j + q];
                if (EPI == 1) t = 0.5f * t * (1.f + erff(t * 0.70710678118654752f));
                e[q] = t;
            }
            float4 v; v.x = e[0]; v.y = e[1]; v.z = e[2]; v.w = e[3];
            *(float4*)(crow + j) = v;
        }
    }
}

// ---------------- residual + LayerNorm, one block per row ------------------
__global__ void k_add_ln(const float* __restrict__ a, const float* __restrict__ bvec,
                         const float* __restrict__ g, const float* __restrict__ beta,
                         float* __restrict__ out)
{
    const int row = blockIdx.x;
    const float* ar = a + (size_t)row * Dd;
    const float* br = bvec + (size_t)row * Dd;
    __shared__ float v[Dd];
    __shared__ float red[256];

    float local = 0.f;
    #pragma unroll
    for (int k = threadIdx.x; k < Dd; k += 256) {
        float t = ar[k] + br[k];
        v[k] = t;
        local += t;
    }
    red[threadIdx.x] = local; __syncthreads();
    #pragma unroll
    for (int s = 128; s; s >>= 1) {
        if (threadIdx.x < s) red[threadIdx.x] += red[threadIdx.x + s];
        __syncthreads();
    }
    const float mu = red[0] * (1.f / Dd);
    __syncthreads();

    local = 0.f;
    #pragma unroll
    for (int k = threadIdx.x; k < Dd; k += 256) {
        float d = v[k] - mu;
        local += d * d;
    }
    red[threadIdx.x] = local; __syncthreads();
    #pragma unroll
    for (int s = 128; s; s >>= 1) {
        if (threadIdx.x < s) red[threadIdx.x] += red[threadIdx.x + s];
        __syncthreads();
    }
    const float rstd = rsqrtf(red[0] * (1.f / Dd) + 1e-5f);

    float* orow = out + (size_t)row * Dd;
    #pragma unroll
    for (int k = threadIdx.x; k < Dd; k += 256)
        orow[k] = (v[k] - mu) * rstd * g[k] + beta[k];
}

// ---------------- host launcher --------------------------------------------
extern "C" void kernel_launch(void* const* d_in, const int* in_sizes, int n_in,
                              void* d_out, int out_size)
{
    const float* nf     = (const float*)d_in[0];
    const int*   adj    = (const int*)  d_in[1];
    const float* attn_w = (const float*)d_in[2];
    const float* attn_b = (const float*)d_in[3];
    const float* W1     = (const float*)d_in[4];
    const float* b1     = (const float*)d_in[5];
    const float* W2     = (const float*)d_in[6];
    const float* b2     = (const float*)d_in[7];
    const float* g1     = (const float*)d_in[8];
    const float* beta1  = (const float*)d_in[9];
    const float* g2     = (const float*)d_in[10];
    const float* beta2  = (const float*)d_in[11];
    float* out = (float*)d_out;

    float *xg, *hg, *attng, *aggg, *hidg, *ffg;
    cudaGetSymbolAddress((void**)&xg,    g_x);
    cudaGetSymbolAddress((void**)&hg,    g_h);
    cudaGetSymbolAddress((void**)&attng, g_attn);
    cudaGetSymbolAddress((void**)&aggg,  g_agg);
    cudaGetSymbolAddress((void**)&hidg,  g_hidden);
    cudaGetSymbolAddress((void**)&ffg,   g_ff);

    for (int l = 0; l < Ll; l++) {
        const float* xin  = (l == 0)      ? nf  : xg;
        float*       xout = (l == Ll - 1) ? out : xg;

        k_scores<<<ROWS / 8, 256>>>(xin, attn_w + (size_t)l * 2 * Dd);
        k_attn<<<ROWS, 256>>>(adj, attn_b + l);

        {   // agg = attn @ x (batched over B)
            dim3 grid(Dd / 128, Nn / 128, Bb);
            k_gemm<0><<<grid, 256>>>(attng, xin, aggg, nullptr,
                                     Nn, Dd, Nn,
                                     (long long)Nn * Nn, (long long)Nn * Dd,
                                     (long long)Nn * Dd);
        }

        k_add_ln<<<ROWS, 256>>>(xin, aggg, g1 + (size_t)l * Dd, beta1 + (size_t)l * Dd, hg);

        {   // hidden = gelu(h @ W1 + b1)
            dim3 grid(Hh / 128, ROWS / 128, 1);
            k_gemm<1><<<grid, 256>>>(hg, W1 + (size_t)l * Dd * Hh, hidg,
                                     b1 + (size_t)l * Hh,
                                     ROWS, Hh, Dd, 0, 0, 0);
        }

        {   // ff = hidden @ W2 + b2
            dim3 grid(Dd / 128, ROWS / 128, 1);
            k_gemm<2><<<grid, 256>>>(hidg, W2 + (size_t)l * Hh * Dd, ffg,
                                     b2 + (size_t)l * Dd,
                                     ROWS, Dd, Hh, 0, 0, 0);
        }

        k_add_ln<<<ROWS, 256>>>(hg, ffg, g2 + (size_t)l * Dd, beta2 + (size_t)l * Dd, xout);
    }
}

// round 10
// speedup vs baseline: 2.9119x; 2.9119x over previous
#include <cuda_runtime.h>
#include <cuda_bf16.h>
#include <math.h>

#define Bb 8
#define Nn 1024
#define Dd 512
#define Hh 2048
#define Ll 3
#define ROWS (Bb*Nn)   // 8192

// ---------------- device scratch (static, allocation-free) ----------------
__device__ float g_x[ROWS * Dd];
__device__ float g_h[ROWS * Dd];
__device__ float g_agg[ROWS * Dd];
__device__ float g_ff[ROWS * Dd];
__device__ float g_si[ROWS];
__device__ float g_sj[ROWS];

__device__ __nv_bfloat16 g_attn_hi[(size_t)Bb * Nn * Nn];
__device__ __nv_bfloat16 g_attn_lo[(size_t)Bb * Nn * Nn];
__device__ __nv_bfloat16 g_h_hi[ROWS * Dd];
__device__ __nv_bfloat16 g_h_lo[ROWS * Dd];
__device__ __nv_bfloat16 g_xT_hi[(size_t)Bb * Dd * Nn];
__device__ __nv_bfloat16 g_xT_lo[(size_t)Bb * Dd * Nn];
__device__ __nv_bfloat16 g_hid_hi[(size_t)ROWS * Hh];
__device__ __nv_bfloat16 g_hid_lo[(size_t)ROWS * Hh];
__device__ __nv_bfloat16 g_W1T_hi[(size_t)Ll * Hh * Dd];
__device__ __nv_bfloat16 g_W1T_lo[(size_t)Ll * Hh * Dd];
__device__ __nv_bfloat16 g_W2T_hi[(size_t)Ll * Dd * Hh];
__device__ __nv_bfloat16 g_W2T_lo[(size_t)Ll * Dd * Hh];

// ---------------- helpers ---------------------------------------------------
__device__ __forceinline__ void bf16split(float x, __nv_bfloat16& h, __nv_bfloat16& l)
{
    h = __float2bfloat16(x);
    l = __float2bfloat16(x - __bfloat162float(h));
}

__device__ __forceinline__ unsigned s2u(const void* p)
{
    unsigned a;
    asm("{ .reg .u64 t; cvta.to.shared.u64 t, %1; cvt.u32.u64 %0, t; }" : "=r"(a) : "l"(p));
    return a;
}

__device__ __forceinline__ void cpasync16(unsigned dst, const void* src)
{
    asm volatile("cp.async.cg.shared.global [%0], [%1], 16;" :: "r"(dst), "l"(src) : "memory");
}

__device__ __forceinline__ void ldsm4(unsigned& r0, unsigned& r1, unsigned& r2, unsigned& r3,
                                      unsigned addr)
{
    asm volatile("ldmatrix.sync.aligned.m8n8.x4.shared.b16 {%0,%1,%2,%3}, [%4];"
                 : "=r"(r0), "=r"(r1), "=r"(r2), "=r"(r3) : "r"(addr));
}

__device__ __forceinline__ void mma16816(float* d, const unsigned* a, const unsigned* b)
{
    asm volatile("mma.sync.aligned.m16n8k16.row.col.f32.bf16.bf16.f32 "
                 "{%0,%1,%2,%3}, {%4,%5,%6,%7}, {%8,%9}, {%0,%1,%2,%3};"
                 : "+f"(d[0]), "+f"(d[1]), "+f"(d[2]), "+f"(d[3])
                 : "r"(a[0]), "r"(a[1]), "r"(a[2]), "r"(a[3]), "r"(b[0]), "r"(b[1]));
}

// ---------------- kernel 1: per-row attention projections si, sj ----------
__global__ void k_scores(const float* __restrict__ x, const float* __restrict__ aw)
{
    int row  = blockIdx.x * 8 + (threadIdx.x >> 5);
    int lane = threadIdx.x & 31;
    const float* xr = x + (size_t)row * Dd;
    float s1 = 0.f, s2 = 0.f;
    #pragma unroll 4
    for (int k = lane; k < Dd; k += 32) {
        float v = xr[k];
        s1 += v * aw[k];
        s2 += v * aw[Dd + k];
    }
    #pragma unroll
    for (int o = 16; o; o >>= 1) {
        s1 += __shfl_xor_sync(0xffffffffu, s1, o);
        s2 += __shfl_xor_sync(0xffffffffu, s2, o);
    }
    if (lane == 0) { g_si[row] = s1; g_sj[row] = s2; }
}

// ---------------- kernel 2: masked softmax -> bf16 hi/lo -------------------
__global__ void k_attn(const int* __restrict__ adj, const float* __restrict__ ab_ptr)
{
    const int row = blockIdx.x;
    const int b = row >> 10;
    const int i = row & 1023;
    const float ab = ab_ptr[0];
    const int* arow = adj + (size_t)row * Nn;
    const float* sjb = g_sj + b * Nn;
    const float si = g_si[row];

    float sc[Nn / 256];
    float lmax = -3.4e38f;
    #pragma unroll
    for (int t = 0; t < Nn / 256; t++) {
        int j = threadIdx.x + t * 256;
        float s = si + sjb[j] + ab;
        s = (s >= 0.f) ? s : 0.2f * s;
        bool ok = (arow[j] != 0) | (j == i);
        s = ok ? s : -3.4e38f;
        sc[t] = s;
        lmax = fmaxf(lmax, s);
    }
    __shared__ float red[256];
    red[threadIdx.x] = lmax; __syncthreads();
    #pragma unroll
    for (int s = 128; s; s >>= 1) {
        if (threadIdx.x < s) red[threadIdx.x] = fmaxf(red[threadIdx.x], red[threadIdx.x + s]);
        __syncthreads();
    }
    const float m = red[0];
    __syncthreads();

    float lsum = 0.f;
    #pragma unroll
    for (int t = 0; t < Nn / 256; t++) {
        float e = (sc[t] <= -3.0e38f) ? 0.f : expf(sc[t] - m);
        sc[t] = e;
        lsum += e;
    }
    red[threadIdx.x] = lsum; __syncthreads();
    #pragma unroll
    for (int s = 128; s; s >>= 1) {
        if (threadIdx.x < s) red[threadIdx.x] += red[threadIdx.x + s];
        __syncthreads();
    }
    const float inv = 1.f / red[0];
    __nv_bfloat16* oh = g_attn_hi + (size_t)row * Nn;
    __nv_bfloat16* ol = g_attn_lo + (size_t)row * Nn;
    #pragma unroll
    for (int t = 0; t < Nn / 256; t++) {
        int j = threadIdx.x + t * 256;
        __nv_bfloat16 h, l;
        bf16split(sc[t] * inv, h, l);
        oh[j] = h; ol[j] = l;
    }
}

// ---------------- transpose + bf16-split: src[R,C] -> dst[C,R] hi/lo -------
__global__ void k_tsplit(const float* __restrict__ src,
                         __nv_bfloat16* __restrict__ dhi,
                         __nv_bfloat16* __restrict__ dlo,
                         int R, int C, long long sSrc, long long sDst)
{
    __shared__ float t[32][33];
    const int z = blockIdx.z;
    src += (size_t)z * sSrc;
    const int c0 = blockIdx.x * 32, r0 = blockIdx.y * 32;
    #pragma unroll
    for (int i = threadIdx.y; i < 32; i += 8)
        t[i][threadIdx.x] = src[(size_t)(r0 + i) * C + c0 + threadIdx.x];
    __syncthreads();
    const size_t dbase = (size_t)z * sDst;
    #pragma unroll
    for (int i = threadIdx.y; i < 32; i += 8) {
        float v = t[threadIdx.x][i];
        __nv_bfloat16 h, l; bf16split(v, h, l);
        size_t o = dbase + (size_t)(c0 + i) * R + r0 + threadIdx.x;
        dhi[o] = h; dlo[o] = l;
    }
}

// ---------------- async smem tile loader (128 rows x 64 bf16, swizzled) ----
// layout: row r (0-127), 16B chunk c (0-7): off = r*128 + ((c ^ (r&7)) * 16)
__device__ __forceinline__ void ldtile_async(const __nv_bfloat16* __restrict__ src,
                                             int K, int kb, unsigned dst, int tid)
{
    #pragma unroll
    for (int it = 0; it < 4; it++) {
        int idx = tid + it * 256;
        int row = idx >> 3, c = idx & 7;
        unsigned off = (unsigned)(row * 128 + ((c ^ (row & 7)) << 4));
        cpasync16(dst + off, src + (size_t)row * K + kb + c * 8);
    }
}

// ---------------- mma.sync bf16x3-split GEMM -------------------------------
// C[m,n] = sum_k A[m,k]*B[n,k]; A=[M,K] hi/lo row-major, B=[N,K] hi/lo row-major.
// EPI: 0 = fp32 store, 1 = bias + gelu -> bf16 hi/lo, 2 = bias -> fp32.
static constexpr int STAGE_BYTES = 65536;          // 4 x 16KB (Ahi,Alo,Bhi,Blo)
static constexpr int GEMM_SMEM   = 2 * STAGE_BYTES;

template <int EPI>
__global__ void __launch_bounds__(256, 1)
k_mma(const __nv_bfloat16* __restrict__ Ahi, const __nv_bfloat16* __restrict__ Alo,
      const __nv_bfloat16* __restrict__ Bhi, const __nv_bfloat16* __restrict__ Blo,
      float* __restrict__ C, __nv_bfloat16* __restrict__ Ohi, __nv_bfloat16* __restrict__ Olo,
      const float* __restrict__ bias, int Ncols, int K,
      long long sA, long long sB, long long sC)
{
    extern __shared__ char smem[];
    const unsigned sb = s2u(smem);
    const int tid = threadIdx.x, wid = tid >> 5, lane = tid & 31;
    const int z = blockIdx.z;
    const int wm = wid & 1, wn = wid >> 1;     // warp grid 2 (m) x 4 (n)

    const __nv_bfloat16* pAH = Ahi + (size_t)z * sA + (size_t)blockIdx.y * 128 * K;
    const __nv_bfloat16* pAL = Alo + (size_t)z * sA + (size_t)blockIdx.y * 128 * K;
    const __nv_bfloat16* pBH = Bhi + (size_t)z * sB + (size_t)blockIdx.x * 128 * K;
    const __nv_bfloat16* pBL = Blo + (size_t)z * sB + (size_t)blockIdx.x * 128 * K;

    float acc[4][4][4];
    #pragma unroll
    for (int a = 0; a < 4; a++)
        #pragma unroll
        for (int b = 0; b < 4; b++)
            #pragma unroll
            for (int c = 0; c < 4; c++) acc[a][b][c] = 0.f;

    // per-lane ldmatrix row indices (within 128-row tile)
    int rA[4], rB[2];
    {
        const int lr = (lane & 7) + ((lane >> 3) & 1) * 8;
        #pragma unroll
        for (int mt = 0; mt < 4; mt++) rA[mt] = wm * 64 + mt * 16 + lr;
        #pragma unroll
        for (int ntp = 0; ntp < 2; ntp++) rB[ntp] = wn * 32 + ntp * 16 + lr;
    }
    const int kc = lane >> 4;    // 0/1: which k-half chunk within a k16 block

    const int NS = K >> 6;

    // prologue: stage 0
    ldtile_async(pAH, K, 0, sb,         tid);
    ldtile_async(pAL, K, 0, sb + 16384, tid);
    ldtile_async(pBH, K, 0, sb + 32768, tid);
    ldtile_async(pBL, K, 0, sb + 49152, tid);
    asm volatile("cp.async.commit_group;" ::: "memory");

    for (int s = 0; s < NS; s++) {
        if (s + 1 < NS) {
            const unsigned nb = sb + ((s + 1) & 1) * STAGE_BYTES;
            const int kb = (s + 1) << 6;
            ldtile_async(pAH, K, kb, nb,         tid);
            ldtile_async(pAL, K, kb, nb + 16384, tid);
            ldtile_async(pBH, K, kb, nb + 32768, tid);
            ldtile_async(pBL, K, kb, nb + 49152, tid);
            asm volatile("cp.async.commit_group;" ::: "memory");
            asm volatile("cp.async.wait_group 1;" ::: "memory");
        } else {
            asm volatile("cp.async.wait_group 0;" ::: "memory");
        }
        __syncthreads();

        const unsigned base = sb + (s & 1) * STAGE_BYTES;
        #pragma unroll
        for (int ks = 0; ks < 4; ks++) {
            unsigned aH[4][4], aL[4][4];
            unsigned bH[4][2], bL[4][2];
            #pragma unroll
            for (int mt = 0; mt < 4; mt++) {
                const int r = rA[mt];
                const unsigned off = (unsigned)(r * 128 + (((ks * 2 + kc) ^ (r & 7)) << 4));
                ldsm4(aH[mt][0], aH[mt][1], aH[mt][2], aH[mt][3], base + off);
                ldsm4(aL[mt][0], aL[mt][1], aL[mt][2], aL[mt][3], base + 16384 + off);
            }
            #pragma unroll
            for (int ntp = 0; ntp < 2; ntp++) {
                const int r = rB[ntp];
                const unsigned off = (unsigned)(r * 128 + (((ks * 2 + kc) ^ (r & 7)) << 4));
                unsigned q0, q1, q2, q3;
                ldsm4(q0, q1, q2, q3, base + 32768 + off);
                bH[ntp * 2 + 0][0] = q0; bH[ntp * 2 + 0][1] = q2;
                bH[ntp * 2 + 1][0] = q1; bH[ntp * 2 + 1][1] = q3;
                ldsm4(q0, q1, q2, q3, base + 49152 + off);
                bL[ntp * 2 + 0][0] = q0; bL[ntp * 2 + 0][1] = q2;
                bL[ntp * 2 + 1][0] = q1; bL[ntp * 2 + 1][1] = q3;
            }
            #pragma unroll
            for (int mt = 0; mt < 4; mt++)
                #pragma unroll
                for (int nt = 0; nt < 4; nt++) {
                    mma16816(acc[mt][nt], aH[mt], bH[nt]);
                    mma16816(acc[mt][nt], aH[mt], bL[nt]);
                    mma16816(acc[mt][nt], aL[mt], bH[nt]);
                }
        }
        __syncthreads();
    }

    // ---------------- epilogue ----------------
    const int mBase = blockIdx.y * 128 + wm * 64;
    const int nBase = blockIdx.x * 128 + wn * 32;
    #pragma unroll
    for (int mt = 0; mt < 4; mt++)
        #pragma unroll
        for (int half = 0; half < 2; half++) {
            const int m = mBase + mt * 16 + (lane >> 2) + half * 8;
            #pragma unroll
            for (int nt = 0; nt < 4; nt++) {
                const int col = nBase + nt * 8 + (lane & 3) * 2;
                float v0 = acc[mt][nt][half * 2 + 0];
                float v1 = acc[mt][nt][half * 2 + 1];
                if (EPI == 0) {
                    float2 v = make_float2(v0, v1);
                    *(float2*)(C + (size_t)z * sC + (size_t)m * Ncols + col) = v;
                } else if (EPI == 2) {
                    float2 v = make_float2(v0 + bias[col], v1 + bias[col + 1]);
                    *(float2*)(C + (size_t)z * sC + (size_t)m * Ncols + col) = v;
                } else {
                    float t0 = v0 + bias[col];
                    float t1 = v1 + bias[col + 1];
                    t0 = 0.5f * t0 * (1.f + erff(t0 * 0.70710678118654752f));
                    t1 = 0.5f * t1 * (1.f + erff(t1 * 0.70710678118654752f));
                    __nv_bfloat16 h0, l0, h1, l1;
                    bf16split(t0, h0, l0);
                    bf16split(t1, h1, l1);
                    unsigned hp = (unsigned)__bfloat16_as_ushort(h0) |
                                  ((unsigned)__bfloat16_as_ushort(h1) << 16);
                    unsigned lp = (unsigned)__bfloat16_as_ushort(l0) |
                                  ((unsigned)__bfloat16_as_ushort(l1) << 16);
                    *(unsigned*)(Ohi + (size_t)m * Ncols + col) = hp;
                    *(unsigned*)(Olo + (size_t)m * Ncols + col) = lp;
                }
            }
        }
}

// ---------------- residual + LayerNorm (optionally emit bf16 hi/lo) -------
template <bool SPLIT>
__global__ void k_add_ln(const float* __restrict__ a, const float* __restrict__ bvec,
                         const float* __restrict__ g, const float* __restrict__ beta,
                         float* __restrict__ out,
                         __nv_bfloat16* __restrict__ ohi, __nv_bfloat16* __restrict__ olo)
{
    const int row = blockIdx.x;
    const float* ar = a + (size_t)row * Dd;
    const float* br = bvec + (size_t)row * Dd;
    __shared__ float v[Dd];
    __shared__ float red[256];

    float local = 0.f;
    #pragma unroll
    for (int k = threadIdx.x; k < Dd; k += 256) {
        float t = ar[k] + br[k];
        v[k] = t;
        local += t;
    }
    red[threadIdx.x] = local; __syncthreads();
    #pragma unroll
    for (int s = 128; s; s >>= 1) {
        if (threadIdx.x < s) red[threadIdx.x] += red[threadIdx.x + s];
        __syncthreads();
    }
    const float mu = red[0] * (1.f / Dd);
    __syncthreads();

    local = 0.f;
    #pragma unroll
    for (int k = threadIdx.x; k < Dd; k += 256) {
        float d = v[k] - mu;
        local += d * d;
    }
    red[threadIdx.x] = local; __syncthreads();
    #pragma unroll
    for (int s = 128; s; s >>= 1) {
        if (threadIdx.x < s) red[threadIdx.x] += red[threadIdx.x + s];
        __syncthreads();
    }
    const float rstd = rsqrtf(red[0] * (1.f / Dd) + 1e-5f);

    float* orow = out + (size_t)row * Dd;
    #pragma unroll
    for (int k = threadIdx.x; k < Dd; k += 256) {
        float t = (v[k] - mu) * rstd * g[k] + beta[k];
        orow[k] = t;
        if (SPLIT) {
            __nv_bfloat16 h, l; bf16split(t, h, l);
            ohi[(size_t)row * Dd + k] = h;
            olo[(size_t)row * Dd + k] = l;
        }
    }
}

// ---------------- host launcher --------------------------------------------
extern "C" void kernel_launch(void* const* d_in, const int* in_sizes, int n_in,
                              void* d_out, int out_size)
{
    const float* nf     = (const float*)d_in[0];
    const int*   adj    = (const int*)  d_in[1];
    const float* attn_w = (const float*)d_in[2];
    const float* attn_b = (const float*)d_in[3];
    const float* W1     = (const float*)d_in[4];
    const float* b1     = (const float*)d_in[5];
    const float* W2     = (const float*)d_in[6];
    const float* b2     = (const float*)d_in[7];
    const float* g1     = (const float*)d_in[8];
    const float* beta1  = (const float*)d_in[9];
    const float* g2     = (const float*)d_in[10];
    const float* beta2  = (const float*)d_in[11];
    float* out = (float*)d_out;

    float *xg, *hg, *aggg, *ffg;
    __nv_bfloat16 *athi, *atlo, *hhi, *hlo, *xthi, *xtlo, *hidhi, *hidlo;
    __nv_bfloat16 *w1thi, *w1tlo, *w2thi, *w2tlo;
    cudaGetSymbolAddress((void**)&xg,    g_x);
    cudaGetSymbolAddress((void**)&hg,    g_h);
    cudaGetSymbolAddress((void**)&aggg,  g_agg);
    cudaGetSymbolAddress((void**)&ffg,   g_ff);
    cudaGetSymbolAddress((void**)&athi,  g_attn_hi);
    cudaGetSymbolAddress((void**)&atlo,  g_attn_lo);
    cudaGetSymbolAddress((void**)&hhi,   g_h_hi);
    cudaGetSymbolAddress((void**)&hlo,   g_h_lo);
    cudaGetSymbolAddress((void**)&xthi,  g_xT_hi);
    cudaGetSymbolAddress((void**)&xtlo,  g_xT_lo);
    cudaGetSymbolAddress((void**)&hidhi, g_hid_hi);
    cudaGetSymbolAddress((void**)&hidlo, g_hid_lo);
    cudaGetSymbolAddress((void**)&w1thi, g_W1T_hi);
    cudaGetSymbolAddress((void**)&w1tlo, g_W1T_lo);
    cudaGetSymbolAddress((void**)&w2thi, g_W2T_hi);
    cudaGetSymbolAddress((void**)&w2tlo, g_W2T_lo);

    cudaFuncSetAttribute(k_mma<0>, cudaFuncAttributeMaxDynamicSharedMemorySize, GEMM_SMEM);
    cudaFuncSetAttribute(k_mma<1>, cudaFuncAttributeMaxDynamicSharedMemorySize, GEMM_SMEM);
    cudaFuncSetAttribute(k_mma<2>, cudaFuncAttributeMaxDynamicSharedMemorySize, GEMM_SMEM);

    const dim3 tb(32, 8);

    // weight transposes + bf16 split
    for (int l = 0; l < Ll; l++) {
        k_tsplit<<<dim3(Hh / 32, Dd / 32, 1), tb>>>(
            W1 + (size_t)l * Dd * Hh, w1thi + (size_t)l * Hh * Dd, w1tlo + (size_t)l * Hh * Dd,
            Dd, Hh, 0, 0);
        k_tsplit<<<dim3(Dd / 32, Hh / 32, 1), tb>>>(
            W2 + (size_t)l * Hh * Dd, w2thi + (size_t)l * Dd * Hh, w2tlo + (size_t)l * Dd * Hh,
            Hh, Dd, 0, 0);
    }

    for (int l = 0; l < Ll; l++) {
        const float* xin  = (l == 0)      ? nf  : xg;
        float*       xout = (l == Ll - 1) ? out : xg;

        k_scores<<<ROWS / 8, 256>>>(xin, attn_w + (size_t)l * 2 * Dd);
        k_attn<<<ROWS, 256>>>(adj, attn_b + l);

        // xT (per batch): [Nn, Dd] -> [Dd, Nn] hi/lo
        k_tsplit<<<dim3(Dd / 32, Nn / 32, Bb), tb>>>(
            xin, xthi, xtlo, Nn, Dd, (long long)Nn * Dd, (long long)Dd * Nn);

        // agg = attn @ x   (batched)
        k_mma<0><<<dim3(Dd / 128, Nn / 128, Bb), 256, GEMM_SMEM>>>(
            athi, atlo, xthi, xtlo, aggg, nullptr, nullptr, nullptr,
            Dd, Nn, (long long)Nn * Nn, (long long)Dd * Nn, (long long)Nn * Dd);

        // h = LN(x + agg), emit fp32 + bf16 hi/lo
        k_add_ln<true><<<ROWS, 256>>>(xin, aggg, g1 + (size_t)l * Dd, beta1 + (size_t)l * Dd,
                                      hg, hhi, hlo);

        // hidden = gelu(h @ W1 + b1) -> bf16 hi/lo
        k_mma<1><<<dim3(Hh / 128, ROWS / 128, 1), 256, GEMM_SMEM>>>(
            hhi, hlo, w1thi + (size_t)l * Hh * Dd, w1tlo + (size_t)l * Hh * Dd,
            nullptr, hidhi, hidlo, b1 + (size_t)l * Hh,
            Hh, Dd, 0, 0, 0);

        // ff = hidden @ W2 + b2 -> fp32
        k_mma<2><<<dim3(Dd / 128, ROWS / 128, 1), 256, GEMM_SMEM>>>(
            hidhi, hidlo, w2thi + (size_t)l * Dd * Hh, w2tlo + (size_t)l * Dd * Hh,
            ffg, nullptr, nullptr, b2 + (size_t)l * Dd,
            Dd, Hh, 0, 0, 0);

        // x = LN(h + ff)
        k_add_ln<false><<<ROWS, 256>>>(hg, ffg, g2 + (size_t)l * Dd, beta2 + (size_t)l * Dd,
                                       xout, nullptr, nullptr);
    }
}

// round 11
// speedup vs baseline: 3.0400x; 1.0440x over previous
#include <cuda_runtime.h>
#include <cuda_bf16.h>
#include <math.h>

#define Bb 8
#define Nn 1024
#define Dd 512
#define Hh 2048
#define Ll 3
#define ROWS (Bb*Nn)   // 8192

// ---------------- device scratch (static, allocation-free) ----------------
__device__ float g_x[ROWS * Dd];
__device__ float g_h[ROWS * Dd];
__device__ float g_agg[ROWS * Dd];
__device__ float g_ff[ROWS * Dd];
__device__ float g_si[ROWS];
__device__ float g_sj[ROWS];

__device__ __nv_bfloat16 g_attn_hi[(size_t)Bb * Nn * Nn];
__device__ __nv_bfloat16 g_attn_lo[(size_t)Bb * Nn * Nn];
__device__ __nv_bfloat16 g_h_hi[ROWS * Dd];
__device__ __nv_bfloat16 g_h_lo[ROWS * Dd];
__device__ __nv_bfloat16 g_xT_hi[(size_t)Bb * Dd * Nn];
__device__ __nv_bfloat16 g_xT_lo[(size_t)Bb * Dd * Nn];
__device__ __nv_bfloat16 g_hid_hi[(size_t)ROWS * Hh];
__device__ __nv_bfloat16 g_hid_lo[(size_t)ROWS * Hh];
__device__ __nv_bfloat16 g_W1T_hi[(size_t)Ll * Hh * Dd];
__device__ __nv_bfloat16 g_W1T_lo[(size_t)Ll * Hh * Dd];
__device__ __nv_bfloat16 g_W2T_hi[(size_t)Ll * Dd * Hh];
__device__ __nv_bfloat16 g_W2T_lo[(size_t)Ll * Dd * Hh];

// ---------------- helpers ---------------------------------------------------
__device__ __forceinline__ void bf16split(float x, __nv_bfloat16& h, __nv_bfloat16& l)
{
    h = __float2bfloat16(x);
    l = __float2bfloat16(x - __bfloat162float(h));
}

__device__ __forceinline__ unsigned s2u(const void* p)
{
    unsigned a;
    asm("{ .reg .u64 t; cvta.to.shared.u64 t, %1; cvt.u32.u64 %0, t; }" : "=r"(a) : "l"(p));
    return a;
}

__device__ __forceinline__ void cpasync16(unsigned dst, const void* src)
{
    asm volatile("cp.async.cg.shared.global [%0], [%1], 16;" :: "r"(dst), "l"(src) : "memory");
}

__device__ __forceinline__ void ldsm4(unsigned& r0, unsigned& r1, unsigned& r2, unsigned& r3,
                                      unsigned addr)
{
    asm volatile("ldmatrix.sync.aligned.m8n8.x4.shared.b16 {%0,%1,%2,%3}, [%4];"
                 : "=r"(r0), "=r"(r1), "=r"(r2), "=r"(r3) : "r"(addr));
}

__device__ __forceinline__ void mma16816(float* d, const unsigned* a, const unsigned* b)
{
    asm volatile("mma.sync.aligned.m16n8k16.row.col.f32.bf16.bf16.f32 "
                 "{%0,%1,%2,%3}, {%4,%5,%6,%7}, {%8,%9}, {%0,%1,%2,%3};"
                 : "+f"(d[0]), "+f"(d[1]), "+f"(d[2]), "+f"(d[3])
                 : "r"(a[0]), "r"(a[1]), "r"(a[2]), "r"(a[3]), "r"(b[0]), "r"(b[1]));
}

// ---------------- kernel 1: per-row attention projections si, sj ----------
__global__ void k_scores(const float* __restrict__ x, const float* __restrict__ aw)
{
    int row  = blockIdx.x * 8 + (threadIdx.x >> 5);
    int lane = threadIdx.x & 31;
    const float* xr = x + (size_t)row * Dd;
    float s1 = 0.f, s2 = 0.f;
    #pragma unroll 4
    for (int k = lane; k < Dd; k += 32) {
        float v = xr[k];
        s1 += v * aw[k];
        s2 += v * aw[Dd + k];
    }
    #pragma unroll
    for (int o = 16; o; o >>= 1) {
        s1 += __shfl_xor_sync(0xffffffffu, s1, o);
        s2 += __shfl_xor_sync(0xffffffffu, s2, o);
    }
    if (lane == 0) { g_si[row] = s1; g_sj[row] = s2; }
}

// ---------------- kernel 2: masked softmax -> bf16 hi/lo (vectorized) ------
__global__ void k_attn(const int* __restrict__ adj, const float* __restrict__ ab_ptr)
{
    const int row = blockIdx.x;
    const int b = row >> 10;
    const int i = row & 1023;
    const int tid = threadIdx.x, lane = tid & 31, wid = tid >> 5;
    const float ab = ab_ptr[0];
    const int jb = tid * 4;

    const int4   a4  = *(const int4*)(adj + (size_t)row * Nn + jb);
    const float4 sj4 = *(const float4*)(g_sj + b * Nn + jb);
    const float si = g_si[row];

    float sc[4];
    {
        const int   av[4] = {a4.x, a4.y, a4.z, a4.w};
        const float sv[4] = {sj4.x, sj4.y, sj4.z, sj4.w};
        #pragma unroll
        for (int q = 0; q < 4; q++) {
            float s = si + sv[q] + ab;
            s = (s >= 0.f) ? s : 0.2f * s;
            bool ok = (av[q] != 0) | ((jb + q) == i);
            sc[q] = ok ? s : -3.4e38f;
        }
    }

    __shared__ float red[8];
    float lmax = fmaxf(fmaxf(sc[0], sc[1]), fmaxf(sc[2], sc[3]));
    #pragma unroll
    for (int o = 16; o; o >>= 1) lmax = fmaxf(lmax, __shfl_xor_sync(0xffffffffu, lmax, o));
    if (lane == 0) red[wid] = lmax;
    __syncthreads();
    float m = red[0];
    #pragma unroll
    for (int w = 1; w < 8; w++) m = fmaxf(m, red[w]);
    __syncthreads();

    float lsum = 0.f;
    #pragma unroll
    for (int q = 0; q < 4; q++) {
        float e = (sc[q] <= -3.0e38f) ? 0.f : expf(sc[q] - m);
        sc[q] = e;
        lsum += e;
    }
    #pragma unroll
    for (int o = 16; o; o >>= 1) lsum += __shfl_xor_sync(0xffffffffu, lsum, o);
    if (lane == 0) red[wid] = lsum;
    __syncthreads();
    float S = 0.f;
    #pragma unroll
    for (int w = 0; w < 8; w++) S += red[w];
    const float inv = 1.f / S;

    unsigned hp[2], lp[2];
    #pragma unroll
    for (int q = 0; q < 4; q += 2) {
        __nv_bfloat16 h0, l0, h1, l1;
        bf16split(sc[q] * inv, h0, l0);
        bf16split(sc[q + 1] * inv, h1, l1);
        hp[q >> 1] = (unsigned)__bfloat16_as_ushort(h0) |
                     ((unsigned)__bfloat16_as_ushort(h1) << 16);
        lp[q >> 1] = (unsigned)__bfloat16_as_ushort(l0) |
                     ((unsigned)__bfloat16_as_ushort(l1) << 16);
    }
    *(uint2*)(g_attn_hi + (size_t)row * Nn + jb) = make_uint2(hp[0], hp[1]);
    *(uint2*)(g_attn_lo + (size_t)row * Nn + jb) = make_uint2(lp[0], lp[1]);
}

// ---------------- transpose + bf16-split: src[R,C] -> dst[C,R] hi/lo -------
__global__ void k_tsplit(const float* __restrict__ src,
                         __nv_bfloat16* __restrict__ dhi,
                         __nv_bfloat16* __restrict__ dlo,
                         int R, int C, long long sSrc, long long sDst)
{
    __shared__ float t[32][33];
    const int z = blockIdx.z;
    src += (size_t)z * sSrc;
    const int c0 = blockIdx.x * 32, r0 = blockIdx.y * 32;
    #pragma unroll
    for (int i = threadIdx.y; i < 32; i += 8)
        t[i][threadIdx.x] = src[(size_t)(r0 + i) * C + c0 + threadIdx.x];
    __syncthreads();
    const size_t dbase = (size_t)z * sDst;
    #pragma unroll
    for (int i = threadIdx.y; i < 32; i += 8) {
        float v = t[threadIdx.x][i];
        __nv_bfloat16 h, l; bf16split(v, h, l);
        size_t o = dbase + (size_t)(c0 + i) * R + r0 + threadIdx.x;
        dhi[o] = h; dlo[o] = l;
    }
}

// ---------------- async smem tile loader (128 rows x 32 bf16, swizzled) ----
// row r (0-127), 16B chunk c (0-3): off = r*64 + ((c ^ ((r>>1)&3)) * 16)
__device__ __forceinline__ void ldtile32_async(const __nv_bfloat16* __restrict__ src,
                                               int K, int kb, unsigned dst, int tid)
{
    #pragma unroll
    for (int it = 0; it < 2; it++) {
        int idx = tid + it * 256;
        int row = idx >> 2, c = idx & 3;
        unsigned off = (unsigned)(row * 64 + ((c ^ ((row >> 1) & 3)) << 4));
        cpasync16(dst + off, src + (size_t)row * K + kb + c * 8);
    }
}

__device__ __forceinline__ void ldstage(const __nv_bfloat16* pAH, const __nv_bfloat16* pAL,
                                        const __nv_bfloat16* pBH, const __nv_bfloat16* pBL,
                                        int K, int kb, unsigned buf, int tid)
{
    ldtile32_async(pAH, K, kb, buf,         tid);
    ldtile32_async(pAL, K, kb, buf + 8192,  tid);
    ldtile32_async(pBH, K, kb, buf + 16384, tid);
    ldtile32_async(pBL, K, kb, buf + 24576, tid);
    asm volatile("cp.async.commit_group;" ::: "memory");
}

// ---------------- mma.sync bf16x3-split GEMM (3-stage, 2 CTA/SM) -----------
// C[m,n] = sum_k A[m,k]*B[n,k]; A=[M,K] hi/lo row-major, B=[N,K] hi/lo row-major.
// EPI: 0 = fp32 store, 1 = bias + gelu -> bf16 hi/lo, 2 = bias -> fp32.
static constexpr int STAGE_BYTES = 32768;          // 4 x 8KB (Ahi,Alo,Bhi,Blo)
static constexpr int GEMM_SMEM   = 3 * STAGE_BYTES;

template <int EPI>
__global__ void __launch_bounds__(256, 2)
k_mma(const __nv_bfloat16* __restrict__ Ahi, const __nv_bfloat16* __restrict__ Alo,
      const __nv_bfloat16* __restrict__ Bhi, const __nv_bfloat16* __restrict__ Blo,
      float* __restrict__ C, __nv_bfloat16* __restrict__ Ohi, __nv_bfloat16* __restrict__ Olo,
      const float* __restrict__ bias, int Ncols, int K,
      long long sA, long long sB, long long sC)
{
    extern __shared__ char smem[];
    const unsigned sb = s2u(smem);
    const int tid = threadIdx.x, wid = tid >> 5, lane = tid & 31;
    const int z = blockIdx.z;
    const int wm = wid & 1, wn = wid >> 1;     // warp grid 2 (m) x 4 (n)

    const __nv_bfloat16* pAH = Ahi + (size_t)z * sA + (size_t)blockIdx.y * 128 * K;
    const __nv_bfloat16* pAL = Alo + (size_t)z * sA + (size_t)blockIdx.y * 128 * K;
    const __nv_bfloat16* pBH = Bhi + (size_t)z * sB + (size_t)blockIdx.x * 128 * K;
    const __nv_bfloat16* pBL = Blo + (size_t)z * sB + (size_t)blockIdx.x * 128 * K;

    float acc[4][4][4];
    #pragma unroll
    for (int a = 0; a < 4; a++)
        #pragma unroll
        for (int b = 0; b < 4; b++)
            #pragma unroll
            for (int c = 0; c < 4; c++) acc[a][b][c] = 0.f;

    // per-lane ldmatrix row indices (within 128-row tile)
    int rA[4], rB[2];
    {
        const int lr = (lane & 7) + ((lane >> 3) & 1) * 8;
        #pragma unroll
        for (int mt = 0; mt < 4; mt++) rA[mt] = wm * 64 + mt * 16 + lr;
        #pragma unroll
        for (int ntp = 0; ntp < 2; ntp++) rB[ntp] = wn * 32 + ntp * 16 + lr;
    }
    const int kc = lane >> 4;    // 0/1: k-half chunk within a k16 block

    const int NS = K >> 5;

    // prologue: stages 0,1
    ldstage(pAH, pAL, pBH, pBL, K, 0, sb, tid);
    ldstage(pAH, pAL, pBH, pBL, K, 32, sb + STAGE_BYTES, tid);

    for (int s = 0; s < NS; s++) {
        __syncthreads();   // all warps done with the buffer being overwritten
        if (s + 2 < NS) {
            ldstage(pAH, pAL, pBH, pBL, K, (s + 2) << 5,
                    sb + ((s + 2) % 3) * STAGE_BYTES, tid);
            asm volatile("cp.async.wait_group 2;" ::: "memory");
        } else if (s + 1 < NS) {
            asm volatile("cp.async.wait_group 1;" ::: "memory");
        } else {
            asm volatile("cp.async.wait_group 0;" ::: "memory");
        }
        __syncthreads();   // stage s visible CTA-wide

        const unsigned base = sb + (s % 3) * STAGE_BYTES;
        #pragma unroll
        for (int ks = 0; ks < 2; ks++) {
            const int ch = ks * 2 + kc;
            unsigned aH[4][4], aL[4][4];
            unsigned bH[4][2], bL[4][2];
            #pragma unroll
            for (int mt = 0; mt < 4; mt++) {
                const int r = rA[mt];
                const unsigned off = (unsigned)(r * 64 + ((ch ^ ((r >> 1) & 3)) << 4));
                ldsm4(aH[mt][0], aH[mt][1], aH[mt][2], aH[mt][3], base + off);
                ldsm4(aL[mt][0], aL[mt][1], aL[mt][2], aL[mt][3], base + 8192 + off);
            }
            #pragma unroll
            for (int ntp = 0; ntp < 2; ntp++) {
                const int r = rB[ntp];
                const unsigned off = (unsigned)(r * 64 + ((ch ^ ((r >> 1) & 3)) << 4));
                unsigned q0, q1, q2, q3;
                ldsm4(q0, q1, q2, q3, base + 16384 + off);
                bH[ntp * 2 + 0][0] = q0; bH[ntp * 2 + 0][1] = q2;
                bH[ntp * 2 + 1][0] = q1; bH[ntp * 2 + 1][1] = q3;
                ldsm4(q0, q1, q2, q3, base + 24576 + off);
                bL[ntp * 2 + 0][0] = q0; bL[ntp * 2 + 0][1] = q2;
                bL[ntp * 2 + 1][0] = q1; bL[ntp * 2 + 1][1] = q3;
            }
            #pragma unroll
            for (int mt = 0; mt < 4; mt++)
                #pragma unroll
                for (int nt = 0; nt < 4; nt++) {
                    mma16816(acc[mt][nt], aH[mt], bH[nt]);
                    mma16816(acc[mt][nt], aH[mt], bL[nt]);
                    mma16816(acc[mt][nt], aL[mt], bH[nt]);
                }
        }
    }

    // ---------------- epilogue ----------------
    const int mBase = blockIdx.y * 128 + wm * 64;
    const int nBase = blockIdx.x * 128 + wn * 32;
    #pragma unroll
    for (int mt = 0; mt < 4; mt++)
        #pragma unroll
        for (int half = 0; half < 2; half++) {
            const int m = mBase + mt * 16 + (lane >> 2) + half * 8;
            #pragma unroll
            for (int nt = 0; nt < 4; nt++) {
                const int col = nBase + nt * 8 + (lane & 3) * 2;
                float v0 = acc[mt][nt][half * 2 + 0];
                float v1 = acc[mt][nt][half * 2 + 1];
                if (EPI == 0) {
                    float2 v = make_float2(v0, v1);
                    *(float2*)(C + (size_t)z * sC + (size_t)m * Ncols + col) = v;
                } else if (EPI == 2) {
                    float2 v = make_float2(v0 + bias[col], v1 + bias[col + 1]);
                    *(float2*)(C + (size_t)z * sC + (size_t)m * Ncols + col) = v;
                } else {
                    float t0 = v0 + bias[col];
                    float t1 = v1 + bias[col + 1];
                    t0 = 0.5f * t0 * (1.f + erff(t0 * 0.70710678118654752f));
                    t1 = 0.5f * t1 * (1.f + erff(t1 * 0.70710678118654752f));
                    __nv_bfloat16 h0, l0, h1, l1;
                    bf16split(t0, h0, l0);
                    bf16split(t1, h1, l1);
                    unsigned hp = (unsigned)__bfloat16_as_ushort(h0) |
                                  ((unsigned)__bfloat16_as_ushort(h1) << 16);
                    unsigned lp = (unsigned)__bfloat16_as_ushort(l0) |
                                  ((unsigned)__bfloat16_as_ushort(l1) << 16);
                    *(unsigned*)(Ohi + (size_t)m * Ncols + col) = hp;
                    *(unsigned*)(Olo + (size_t)m * Ncols + col) = lp;
                }
            }
        }
}

// ---------------- residual + LayerNorm (float2, one-pass stats) ------------
template <bool SPLIT>
__global__ void k_add_ln(const float* __restrict__ a, const float* __restrict__ bvec,
                         const float* __restrict__ g, const float* __restrict__ beta,
                         float* __restrict__ out,
                         __nv_bfloat16* __restrict__ ohi, __nv_bfloat16* __restrict__ olo)
{
    const int row = blockIdx.x;
    const int tid = threadIdx.x, lane = tid & 31, wid = tid >> 5;
    const size_t base = (size_t)row * Dd + tid * 2;

    const float2 a2 = *(const float2*)(a + base);
    const float2 b2 = *(const float2*)(bvec + base);
    const float x0 = a2.x + b2.x, x1 = a2.y + b2.y;

    float s = x0 + x1;
    float q = x0 * x0 + x1 * x1;
    #pragma unroll
    for (int o = 16; o; o >>= 1) {
        s += __shfl_xor_sync(0xffffffffu, s, o);
        q += __shfl_xor_sync(0xffffffffu, q, o);
    }
    __shared__ float ss[8], sq[8];
    if (lane == 0) { ss[wid] = s; sq[wid] = q; }
    __syncthreads();
    float S = 0.f, Q = 0.f;
    #pragma unroll
    for (int w = 0; w < 8; w++) { S += ss[w]; Q += sq[w]; }

    const float mu = S * (1.f / Dd);
    const float var = Q * (1.f / Dd) - mu * mu;
    const float rstd = rsqrtf(var + 1e-5f);

    const float2 gv = *(const float2*)(g + tid * 2);
    const float2 bv = *(const float2*)(beta + tid * 2);
    const float y0 = (x0 - mu) * rstd * gv.x + bv.x;
    const float y1 = (x1 - mu) * rstd * gv.y + bv.y;
    *(float2*)(out + base) = make_float2(y0, y1);

    if (SPLIT) {
        __nv_bfloat16 h0, l0, h1, l1;
        bf16split(y0, h0, l0);
        bf16split(y1, h1, l1);
        unsigned hp = (unsigned)__bfloat16_as_ushort(h0) |
                      ((unsigned)__bfloat16_as_ushort(h1) << 16);
        unsigned lp = (unsigned)__bfloat16_as_ushort(l0) |
                      ((unsigned)__bfloat16_as_ushort(l1) << 16);
        *(unsigned*)(ohi + base) = hp;
        *(unsigned*)(olo + base) = lp;
    }
}

// ---------------- host launcher --------------------------------------------
extern "C" void kernel_launch(void* const* d_in, const int* in_sizes, int n_in,
                              void* d_out, int out_size)
{
    const float* nf     = (const float*)d_in[0];
    const int*   adj    = (const int*)  d_in[1];
    const float* attn_w = (const float*)d_in[2];
    const float* attn_b = (const float*)d_in[3];
    const float* W1     = (const float*)d_in[4];
    const float* b1     = (const float*)d_in[5];
    const float* W2     = (const float*)d_in[6];
    const float* b2     = (const float*)d_in[7];
    const float* g1     = (const float*)d_in[8];
    const float* beta1  = (const float*)d_in[9];
    const float* g2     = (const float*)d_in[10];
    const float* beta2  = (const float*)d_in[11];
    float* out = (float*)d_out;

    float *xg, *hg, *aggg, *ffg;
    __nv_bfloat16 *athi, *atlo, *hhi, *hlo, *xthi, *xtlo, *hidhi, *hidlo;
    __nv_bfloat16 *w1thi, *w1tlo, *w2thi, *w2tlo;
    cudaGetSymbolAddress((void**)&xg,    g_x);
    cudaGetSymbolAddress((void**)&hg,    g_h);
    cudaGetSymbolAddress((void**)&aggg,  g_agg);
    cudaGetSymbolAddress((void**)&ffg,   g_ff);
    cudaGetSymbolAddress((void**)&athi,  g_attn_hi);
    cudaGetSymbolAddress((void**)&atlo,  g_attn_lo);
    cudaGetSymbolAddress((void**)&hhi,   g_h_hi);
    cudaGetSymbolAddress((void**)&hlo,   g_h_lo);
    cudaGetSymbolAddress((void**)&xthi,  g_xT_hi);
    cudaGetSymbolAddress((void**)&xtlo,  g_xT_lo);
    cudaGetSymbolAddress((void**)&hidhi, g_hid_hi);
    cudaGetSymbolAddress((void**)&hidlo, g_hid_lo);
    cudaGetSymbolAddress((void**)&w1thi, g_W1T_hi);
    cudaGetSymbolAddress((void**)&w1tlo, g_W1T_lo);
    cudaGetSymbolAddress((void**)&w2thi, g_W2T_hi);
    cudaGetSymbolAddress((void**)&w2tlo, g_W2T_lo);

    cudaFuncSetAttribute(k_mma<0>, cudaFuncAttributeMaxDynamicSharedMemorySize, GEMM_SMEM);
    cudaFuncSetAttribute(k_mma<1>, cudaFuncAttributeMaxDynamicSharedMemorySize, GEMM_SMEM);
    cudaFuncSetAttribute(k_mma<2>, cudaFuncAttributeMaxDynamicSharedMemorySize, GEMM_SMEM);

    const dim3 tb(32, 8);

    // weight transposes + bf16 split
    for (int l = 0; l < Ll; l++) {
        k_tsplit<<<dim3(Hh / 32, Dd / 32, 1), tb>>>(
            W1 + (size_t)l * Dd * Hh, w1thi + (size_t)l * Hh * Dd, w1tlo + (size_t)l * Hh * Dd,
            Dd, Hh, 0, 0);
        k_tsplit<<<dim3(Dd / 32, Hh / 32, 1), tb>>>(
            W2 + (size_t)l * Hh * Dd, w2thi + (size_t)l * Dd * Hh, w2tlo + (size_t)l * Dd * Hh,
            Hh, Dd, 0, 0);
    }

    for (int l = 0; l < Ll; l++) {
        const float* xin  = (l == 0)      ? nf  : xg;
        float*       xout = (l == Ll - 1) ? out : xg;

        k_scores<<<ROWS / 8, 256>>>(xin, attn_w + (size_t)l * 2 * Dd);
        k_attn<<<ROWS, 256>>>(adj, attn_b + l);

        // xT (per batch): [Nn, Dd] -> [Dd, Nn] hi/lo
        k_tsplit<<<dim3(Dd / 32, Nn / 32, Bb), tb>>>(
            xin, xthi, xtlo, Nn, Dd, (long long)Nn * Dd, (long long)Dd * Nn);

        // agg = attn @ x   (batched)
        k_mma<0><<<dim3(Dd / 128, Nn / 128, Bb), 256, GEMM_SMEM>>>(
            athi, atlo, xthi, xtlo, aggg, nullptr, nullptr, nullptr,
            Dd, Nn, (long long)Nn * Nn, (long long)Dd * Nn, (long long)Nn * Dd);

        // h = LN(x + agg), emit fp32 + bf16 hi/lo
        k_add_ln<true><<<ROWS, 256>>>(xin, aggg, g1 + (size_t)l * Dd, beta1 + (size_t)l * Dd,
                                      hg, hhi, hlo);

        // hidden = gelu(h @ W1 + b1) -> bf16 hi/lo
        k_mma<1><<<dim3(Hh / 128, ROWS / 128, 1), 256, GEMM_SMEM>>>(
            hhi, hlo, w1thi + (size_t)l * Hh * Dd, w1tlo + (size_t)l * Hh * Dd,
            nullptr, hidhi, hidlo, b1 + (size_t)l * Hh,
            Hh, Dd, 0, 0, 0);

        // ff = hidden @ W2 + b2 -> fp32
        k_mma<2><<<dim3(Dd / 128, ROWS / 128, 1), 256, GEMM_SMEM>>>(
            hidhi, hidlo, w2thi + (size_t)l * Dd * Hh, w2tlo + (size_t)l * Dd * Hh,
            ffg, nullptr, nullptr, b2 + (size_t)l * Dd,
            Dd, Hh, 0, 0, 0);

        // x = LN(h + ff)
        k_add_ln<false><<<ROWS, 256>>>(hg, ffg, g2 + (size_t)l * Dd, beta2 + (size_t)l * Dd,
                                       xout, nullptr, nullptr);
    }
}

// round 13
// speedup vs baseline: 3.0617x; 1.0072x over previous
#include <cuda_runtime.h>
#include <cuda_bf16.h>
#include <math.h>

#define Bb 8
#define Nn 1024
#define Dd 512
#define Hh 2048
#define Ll 3
#define ROWS (Bb*Nn)   // 8192

// ---------------- device scratch (static, allocation-free) ----------------
__device__ float g_x[ROWS * Dd];
__device__ float g_h[ROWS * Dd];
__device__ float g_agg[ROWS * Dd];
__device__ float g_ff[ROWS * Dd];
__device__ float g_si[ROWS];
__device__ float g_sj[ROWS];

__device__ __nv_bfloat16 g_attn_hi[(size_t)Bb * Nn * Nn];
__device__ __nv_bfloat16 g_attn_lo[(size_t)Bb * Nn * Nn];
__device__ __nv_bfloat16 g_h_hi[ROWS * Dd];
__device__ __nv_bfloat16 g_h_lo[ROWS * Dd];
__device__ __nv_bfloat16 g_xT_hi[(size_t)Bb * Dd * Nn];
__device__ __nv_bfloat16 g_xT_lo[(size_t)Bb * Dd * Nn];
__device__ __nv_bfloat16 g_hid_hi[(size_t)ROWS * Hh];
__device__ __nv_bfloat16 g_hid_lo[(size_t)ROWS * Hh];
__device__ __nv_bfloat16 g_W1T_hi[(size_t)Ll * Hh * Dd];
__device__ __nv_bfloat16 g_W1T_lo[(size_t)Ll * Hh * Dd];
__device__ __nv_bfloat16 g_W2T_hi[(size_t)Ll * Dd * Hh];
__device__ __nv_bfloat16 g_W2T_lo[(size_t)Ll * Dd * Hh];

// ---------------- helpers ---------------------------------------------------
__device__ __forceinline__ void bf16split(float x, __nv_bfloat16& h, __nv_bfloat16& l)
{
    h = __float2bfloat16(x);
    l = __float2bfloat16(x - __bfloat162float(h));
}

__device__ __forceinline__ unsigned s2u(const void* p)
{
    unsigned a;
    asm("{ .reg .u64 t; cvta.to.shared.u64 t, %1; cvt.u32.u64 %0, t; }" : "=r"(a) : "l"(p));
    return a;
}

__device__ __forceinline__ void cpasync16(unsigned dst, const void* src)
{
    asm volatile("cp.async.cg.shared.global [%0], [%1], 16;" :: "r"(dst), "l"(src) : "memory");
}

__device__ __forceinline__ void ldsm4(unsigned& r0, unsigned& r1, unsigned& r2, unsigned& r3,
                                      unsigned addr)
{
    asm volatile("ldmatrix.sync.aligned.m8n8.x4.shared.b16 {%0,%1,%2,%3}, [%4];"
                 : "=r"(r0), "=r"(r1), "=r"(r2), "=r"(r3) : "r"(addr));
}

__device__ __forceinline__ void mma16816(float* d, const unsigned* a, const unsigned* b)
{
    asm volatile("mma.sync.aligned.m16n8k16.row.col.f32.bf16.bf16.f32 "
                 "{%0,%1,%2,%3}, {%4,%5,%6,%7}, {%8,%9}, {%0,%1,%2,%3};"
                 : "+f"(d[0]), "+f"(d[1]), "+f"(d[2]), "+f"(d[3])
                 : "r"(a[0]), "r"(a[1]), "r"(a[2]), "r"(a[3]), "r"(b[0]), "r"(b[1]));
}

// ---------------- kernel 1: per-row attention projections si, sj ----------
__global__ void k_scores(const float* __restrict__ x, const float* __restrict__ aw)
{
    int row  = blockIdx.x * 8 + (threadIdx.x >> 5);
    int lane = threadIdx.x & 31;
    const float* xr = x + (size_t)row * Dd;
    float s1 = 0.f, s2 = 0.f;
    #pragma unroll 4
    for (int k = lane; k < Dd; k += 32) {
        float v = xr[k];
        s1 += v * aw[k];
        s2 += v * aw[Dd + k];
    }
    #pragma unroll
    for (int o = 16; o; o >>= 1) {
        s1 += __shfl_xor_sync(0xffffffffu, s1, o);
        s2 += __shfl_xor_sync(0xffffffffu, s2, o);
    }
    if (lane == 0) { g_si[row] = s1; g_sj[row] = s2; }
}

// ---------------- kernel 2: masked softmax -> bf16 hi/lo (vectorized) ------
__global__ void k_attn(const int* __restrict__ adj, const float* __restrict__ ab_ptr)
{
    const int row = blockIdx.x;
    const int b = row >> 10;
    const int i = row & 1023;
    const int tid = threadIdx.x, lane = tid & 31, wid = tid >> 5;
    const float ab = ab_ptr[0];
    const int jb = tid * 4;

    const int4   a4  = *(const int4*)(adj + (size_t)row * Nn + jb);
    const float4 sj4 = *(const float4*)(g_sj + b * Nn + jb);
    const float si = g_si[row];

    float sc[4];
    {
        const int   av[4] = {a4.x, a4.y, a4.z, a4.w};
        const float sv[4] = {sj4.x, sj4.y, sj4.z, sj4.w};
        #pragma unroll
        for (int q = 0; q < 4; q++) {
            float s = si + sv[q] + ab;
            s = (s >= 0.f) ? s : 0.2f * s;
            bool ok = (av[q] != 0) | ((jb + q) == i);
            sc[q] = ok ? s : -3.4e38f;
        }
    }

    __shared__ float red[8];
    float lmax = fmaxf(fmaxf(sc[0], sc[1]), fmaxf(sc[2], sc[3]));
    #pragma unroll
    for (int o = 16; o; o >>= 1) lmax = fmaxf(lmax, __shfl_xor_sync(0xffffffffu, lmax, o));
    if (lane == 0) red[wid] = lmax;
    __syncthreads();
    float m = red[0];
    #pragma unroll
    for (int w = 1; w < 8; w++) m = fmaxf(m, red[w]);
    __syncthreads();

    float lsum = 0.f;
    #pragma unroll
    for (int q = 0; q < 4; q++) {
        float e = (sc[q] <= -3.0e38f) ? 0.f : expf(sc[q] - m);
        sc[q] = e;
        lsum += e;
    }
    #pragma unroll
    for (int o = 16; o; o >>= 1) lsum += __shfl_xor_sync(0xffffffffu, lsum, o);
    if (lane == 0) red[wid] = lsum;
    __syncthreads();
    float S = 0.f;
    #pragma unroll
    for (int w = 0; w < 8; w++) S += red[w];
    const float inv = 1.f / S;

    unsigned hp[2], lp[2];
    #pragma unroll
    for (int q = 0; q < 4; q += 2) {
        __nv_bfloat16 h0, l0, h1, l1;
        bf16split(sc[q] * inv, h0, l0);
        bf16split(sc[q + 1] * inv, h1, l1);
        hp[q >> 1] = (unsigned)__bfloat16_as_ushort(h0) |
                     ((unsigned)__bfloat16_as_ushort(h1) << 16);
        lp[q >> 1] = (unsigned)__bfloat16_as_ushort(l0) |
                     ((unsigned)__bfloat16_as_ushort(l1) << 16);
    }
    *(uint2*)(g_attn_hi + (size_t)row * Nn + jb) = make_uint2(hp[0], hp[1]);
    *(uint2*)(g_attn_lo + (size_t)row * Nn + jb) = make_uint2(lp[0], lp[1]);
}

// ---------------- transpose + bf16-split: src[R,C] -> dst[C,R] hi/lo -------
__global__ void k_tsplit(const float* __restrict__ src,
                         __nv_bfloat16* __restrict__ dhi,
                         __nv_bfloat16* __restrict__ dlo,
                         int R, int C, long long sSrc, long long sDst)
{
    __shared__ float t[32][33];
    const int z = blockIdx.z;
    src += (size_t)z * sSrc;
    const int c0 = blockIdx.x * 32, r0 = blockIdx.y * 32;
    #pragma unroll
    for (int i = threadIdx.y; i < 32; i += 8)
        t[i][threadIdx.x] = src[(size_t)(r0 + i) * C + c0 + threadIdx.x];
    __syncthreads();
    const size_t dbase = (size_t)z * sDst;
    #pragma unroll
    for (int i = threadIdx.y; i < 32; i += 8) {
        float v = t[threadIdx.x][i];
        __nv_bfloat16 h, l; bf16split(v, h, l);
        size_t o = dbase + (size_t)(c0 + i) * R + r0 + threadIdx.x;
        dhi[o] = h; dlo[o] = l;
    }
}

// ---------------- async smem tile loader (128 rows x 64 bf16, swizzled) ----
// row r (0-127), 16B chunk c (0-7): off = r*128 + ((c ^ (r&7)) * 16)
__device__ __forceinline__ void ldtile_async(const __nv_bfloat16* __restrict__ src,
                                             int K, int kb, unsigned dst, int tid)
{
    #pragma unroll
    for (int it = 0; it < 4; it++) {
        int idx = tid + it * 256;
        int row = idx >> 3, c = idx & 7;
        unsigned off = (unsigned)(row * 128 + ((c ^ (row & 7)) << 4));
        cpasync16(dst + off, src + (size_t)row * K + kb + c * 8);
    }
}

__device__ __forceinline__ void ldstage(const __nv_bfloat16* pAH, const __nv_bfloat16* pAL,
                                        const __nv_bfloat16* pBH, const __nv_bfloat16* pBL,
                                        int K, int kb, unsigned buf, int tid)
{
    ldtile_async(pAH, K, kb, buf,         tid);
    ldtile_async(pAL, K, kb, buf + 16384, tid);
    ldtile_async(pBH, K, kb, buf + 32768, tid);
    ldtile_async(pBL, K, kb, buf + 49152, tid);
    asm volatile("cp.async.commit_group;" ::: "memory");
}

// fragment load for one k16 step (chunk pair ch*2 + kc)
__device__ __forceinline__ void ldfrag(unsigned base, int ch, int kc,
                                       const int* rA, const int* rB,
                                       unsigned aH[4][4], unsigned aL[4][4],
                                       unsigned bH[4][2], unsigned bL[4][2])
{
    #pragma unroll
    for (int mt = 0; mt < 4; mt++) {
        const int r = rA[mt];
        const unsigned off = (unsigned)(r * 128 + (((ch * 2 + kc) ^ (r & 7)) << 4));
        ldsm4(aH[mt][0], aH[mt][1], aH[mt][2], aH[mt][3], base + off);
        ldsm4(aL[mt][0], aL[mt][1], aL[mt][2], aL[mt][3], base + 16384 + off);
    }
    #pragma unroll
    for (int ntp = 0; ntp < 2; ntp++) {
        const int r = rB[ntp];
        const unsigned off = (unsigned)(r * 128 + (((ch * 2 + kc) ^ (r & 7)) << 4));
        unsigned q0, q1, q2, q3;
        ldsm4(q0, q1, q2, q3, base + 32768 + off);
        bH[ntp * 2 + 0][0] = q0; bH[ntp * 2 + 0][1] = q2;
        bH[ntp * 2 + 1][0] = q1; bH[ntp * 2 + 1][1] = q3;
        ldsm4(q0, q1, q2, q3, base + 49152 + off);
        bL[ntp * 2 + 0][0] = q0; bL[ntp * 2 + 0][1] = q2;
        bL[ntp * 2 + 1][0] = q1; bL[ntp * 2 + 1][1] = q3;
    }
}

// ---------------- mma.sync bf16x3-split GEMM (3-stage BK=64, frag pipeline) -
// C[m,n] = sum_k A[m,k]*B[n,k]; A=[M,K] hi/lo row-major, B=[N,K] hi/lo row-major.
// EPI: 0 = fp32 store, 1 = bias + gelu -> bf16 hi/lo, 2 = bias -> fp32.
static constexpr int STAGE_BYTES = 65536;          // 4 x 16KB (Ahi,Alo,Bhi,Blo)
static constexpr int GEMM_SMEM   = 3 * STAGE_BYTES;  // 192 KB, occ 1

template <int EPI>
__global__ void __launch_bounds__(256, 1)
k_mma(const __nv_bfloat16* __restrict__ Ahi, const __nv_bfloat16* __restrict__ Alo,
      const __nv_bfloat16* __restrict__ Bhi, const __nv_bfloat16* __restrict__ Blo,
      float* __restrict__ C, __nv_bfloat16* __restrict__ Ohi, __nv_bfloat16* __restrict__ Olo,
      const float* __restrict__ bias, int Ncols, int K,
      long long sA, long long sB, long long sC)
{
    extern __shared__ char smem[];
    const unsigned sb = s2u(smem);
    const int tid = threadIdx.x, wid = tid >> 5, lane = tid & 31;
    const int z = blockIdx.z;
    const int wm = wid & 1, wn = wid >> 1;     // warp grid 2 (m) x 4 (n)

    const __nv_bfloat16* pAH = Ahi + (size_t)z * sA + (size_t)blockIdx.y * 128 * K;
    const __nv_bfloat16* pAL = Alo + (size_t)z * sA + (size_t)blockIdx.y * 128 * K;
    const __nv_bfloat16* pBH = Bhi + (size_t)z * sB + (size_t)blockIdx.x * 128 * K;
    const __nv_bfloat16* pBL = Blo + (size_t)z * sB + (size_t)blockIdx.x * 128 * K;

    float acc[4][4][4];
    #pragma unroll
    for (int a = 0; a < 4; a++)
        #pragma unroll
        for (int b = 0; b < 4; b++)
            #pragma unroll
            for (int c = 0; c < 4; c++) acc[a][b][c] = 0.f;

    // per-lane ldmatrix row indices (within 128-row tile)
    int rA[4], rB[2];
    {
        const int lr = (lane & 7) + ((lane >> 3) & 1) * 8;
        #pragma unroll
        for (int mt = 0; mt < 4; mt++) rA[mt] = wm * 64 + mt * 16 + lr;
        #pragma unroll
        for (int ntp = 0; ntp < 2; ntp++) rB[ntp] = wn * 32 + ntp * 16 + lr;
    }
    const int kc = lane >> 4;    // 0/1: k-half chunk within a k16 block

    const int NS = K >> 6;

    // double-buffered fragments
    unsigned aH[2][4][4], aL[2][4][4], bH[2][4][2], bL[2][4][2];

    // prologue: stages 0,1 in flight
    ldstage(pAH, pAL, pBH, pBL, K, 0, sb, tid);
    if (NS > 1) ldstage(pAH, pAL, pBH, pBL, K, 64, sb + STAGE_BYTES, tid);

    for (int s = 0; s < NS; s++) {
        if (s > 0) __syncthreads();        // all warps done reading stage s-1
        if (s + 2 < NS)
            ldstage(pAH, pAL, pBH, pBL, K, (s + 2) << 6,
                    sb + ((s + 2) % 3) * STAGE_BYTES, tid);
        if (s + 2 < NS) {
            asm volatile("cp.async.wait_group 2;" ::: "memory");
        } else if (s + 1 < NS) {
            asm volatile("cp.async.wait_group 1;" ::: "memory");
        } else {
            asm volatile("cp.async.wait_group 0;" ::: "memory");
        }
        __syncthreads();                   // stage s visible CTA-wide

        const unsigned base = sb + (s % 3) * STAGE_BYTES;
        ldfrag(base, 0, kc, rA, rB, aH[0], aL[0], bH[0], bL[0]);
        #pragma unroll
        for (int ks = 0; ks < 4; ks++) {
            const int cur = ks & 1;
            if (ks < 3)
                ldfrag(base, ks + 1, kc, rA, rB,
                       aH[cur ^ 1], aL[cur ^ 1], bH[cur ^ 1], bL[cur ^ 1]);
            #pragma unroll
            for (int mt = 0; mt < 4; mt++)
                #pragma unroll
                for (int nt = 0; nt < 4; nt++) {
                    mma16816(acc[mt][nt], aH[cur][mt], bH[cur][nt]);
                    mma16816(acc[mt][nt], aH[cur][mt], bL[cur][nt]);
                    mma16816(acc[mt][nt], aL[cur][mt], bH[cur][nt]);
                }
        }
    }

    // ---------------- epilogue ----------------
    const int mBase = blockIdx.y * 128 + wm * 64;
    const int nBase = blockIdx.x * 128 + wn * 32;
    #pragma unroll
    for (int mt = 0; mt < 4; mt++)
        #pragma unroll
        for (int half = 0; half < 2; half++) {
            const int m = mBase + mt * 16 + (lane >> 2) + half * 8;
            #pragma unroll
            for (int nt = 0; nt < 4; nt++) {
                const int col = nBase + nt * 8 + (lane & 3) * 2;
                float v0 = acc[mt][nt][half * 2 + 0];
                float v1 = acc[mt][nt][half * 2 + 1];
                if (EPI == 0) {
                    float2 v = make_float2(v0, v1);
                    *(float2*)(C + (size_t)z * sC + (size_t)m * Ncols + col) = v;
                } else if (EPI == 2) {
                    float2 v = make_float2(v0 + bias[col], v1 + bias[col + 1]);
                    *(float2*)(C + (size_t)z * sC + (size_t)m * Ncols + col) = v;
                } else {
                    float t0 = v0 + bias[col];
                    float t1 = v1 + bias[col + 1];
                    t0 = 0.5f * t0 * (1.f + erff(t0 * 0.70710678118654752f));
                    t1 = 0.5f * t1 * (1.f + erff(t1 * 0.70710678118654752f));
                    __nv_bfloat16 h0, l0, h1, l1;
                    bf16split(t0, h0, l0);
                    bf16split(t1, h1, l1);
                    unsigned hp = (unsigned)__bfloat16_as_ushort(h0) |
                                  ((unsigned)__bfloat16_as_ushort(h1) << 16);
                    unsigned lp = (unsigned)__bfloat16_as_ushort(l0) |
                                  ((unsigned)__bfloat16_as_ushort(l1) << 16);
                    *(unsigned*)(Ohi + (size_t)m * Ncols + col) = hp;
                    *(unsigned*)(Olo + (size_t)m * Ncols + col) = lp;
                }
            }
        }
}

// ---------------- residual + LayerNorm (float2, one-pass stats) ------------
template <bool SPLIT>
__global__ void k_add_ln(const float* __restrict__ a, const float* __restrict__ bvec,
                         const float* __restrict__ g, const float* __restrict__ beta,
                         float* __restrict__ out,
                         __nv_bfloat16* __restrict__ ohi, __nv_bfloat16* __restrict__ olo)
{
    const int row = blockIdx.x;
    const int tid = threadIdx.x, lane = tid & 31, wid = tid >> 5;
    const size_t base = (size_t)row * Dd + tid * 2;

    const float2 a2 = *(const float2*)(a + base);
    const float2 b2 = *(const float2*)(bvec + base);
    const float x0 = a2.x + b2.x, x1 = a2.y + b2.y;

    float s = x0 + x1;
    float q = x0 * x0 + x1 * x1;
    #pragma unroll
    for (int o = 16; o; o >>= 1) {
        s += __shfl_xor_sync(0xffffffffu, s, o);
        q += __shfl_xor_sync(0xffffffffu, q, o);
    }
    __shared__ float ss[8], sq[8];
    if (lane == 0) { ss[wid] = s; sq[wid] = q; }
    __syncthreads();
    float S = 0.f, Q = 0.f;
    #pragma unroll
    for (int w = 0; w < 8; w++) { S += ss[w]; Q += sq[w]; }

    const float mu = S * (1.f / Dd);
    const float var = Q * (1.f / Dd) - mu * mu;
    const float rstd = rsqrtf(var + 1e-5f);

    const float2 gv = *(const float2*)(g + tid * 2);
    const float2 bv = *(const float2*)(beta + tid * 2);
    const float y0 = (x0 - mu) * rstd * gv.x + bv.x;
    const float y1 = (x1 - mu) * rstd * gv.y + bv.y;
    *(float2*)(out + base) = make_float2(y0, y1);

    if (SPLIT) {
        __nv_bfloat16 h0, l0, h1, l1;
        bf16split(y0, h0, l0);
        bf16split(y1, h1, l1);
        unsigned hp = (unsigned)__bfloat16_as_ushort(h0) |
                      ((unsigned)__bfloat16_as_ushort(h1) << 16);
        unsigned lp = (unsigned)__bfloat16_as_ushort(l0) |
                      ((unsigned)__bfloat16_as_ushort(l1) << 16);
        *(unsigned*)(ohi + base) = hp;
        *(unsigned*)(olo + base) = lp;
    }
}

// ---------------- host launcher --------------------------------------------
extern "C" void kernel_launch(void* const* d_in, const int* in_sizes, int n_in,
                              void* d_out, int out_size)
{
    const float* nf     = (const float*)d_in[0];
    const int*   adj    = (const int*)  d_in[1];
    const float* attn_w = (const float*)d_in[2];
    const float* attn_b = (const float*)d_in[3];
    const float* W1     = (const float*)d_in[4];
    const float* b1     = (const float*)d_in[5];
    const float* W2     = (const float*)d_in[6];
    const float* b2     = (const float*)d_in[7];
    const float* g1     = (const float*)d_in[8];
    const float* beta1  = (const float*)d_in[9];
    const float* g2     = (const float*)d_in[10];
    const float* beta2  = (const float*)d_in[11];
    float* out = (float*)d_out;

    float *xg, *hg, *aggg, *ffg;
    __nv_bfloat16 *athi, *atlo, *hhi, *hlo, *xthi, *xtlo, *hidhi, *hidlo;
    __nv_bfloat16 *w1thi, *w1tlo, *w2thi, *w2tlo;
    cudaGetSymbolAddress((void**)&xg,    g_x);
    cudaGetSymbolAddress((void**)&hg,    g_h);
    cudaGetSymbolAddress((void**)&aggg,  g_agg);
    cudaGetSymbolAddress((void**)&ffg,   g_ff);
    cudaGetSymbolAddress((void**)&athi,  g_attn_hi);
    cudaGetSymbolAddress((void**)&atlo,  g_attn_lo);
    cudaGetSymbolAddress((void**)&hhi,   g_h_hi);
    cudaGetSymbolAddress((void**)&hlo,   g_h_lo);
    cudaGetSymbolAddress((void**)&xthi,  g_xT_hi);
    cudaGetSymbolAddress((void**)&xtlo,  g_xT_lo);
    cudaGetSymbolAddress((void**)&hidhi, g_hid_hi);
    cudaGetSymbolAddress((void**)&hidlo, g_hid_lo);
    cudaGetSymbolAddress((void**)&w1thi, g_W1T_hi);
    cudaGetSymbolAddress((void**)&w1tlo, g_W1T_lo);
    cudaGetSymbolAddress((void**)&w2thi, g_W2T_hi);
    cudaGetSymbolAddress((void**)&w2tlo, g_W2T_lo);

    cudaFuncSetAttribute(k_mma<0>, cudaFuncAttributeMaxDynamicSharedMemorySize, GEMM_SMEM);
    cudaFuncSetAttribute(k_mma<1>, cudaFuncAttributeMaxDynamicSharedMemorySize, GEMM_SMEM);
    cudaFuncSetAttribute(k_mma<2>, cudaFuncAttributeMaxDynamicSharedMemorySize, GEMM_SMEM);

    const dim3 tb(32, 8);

    // weight transposes + bf16 split
    for (int l = 0; l < Ll; l++) {
        k_tsplit<<<dim3(Hh / 32, Dd / 32, 1), tb>>>(
            W1 + (size_t)l * Dd * Hh, w1thi + (size_t)l * Hh * Dd, w1tlo + (size_t)l * Hh * Dd,
            Dd, Hh, 0, 0);
        k_tsplit<<<dim3(Dd / 32, Hh / 32, 1), tb>>>(
            W2 + (size_t)l * Hh * Dd, w2thi + (size_t)l * Dd * Hh, w2tlo + (size_t)l * Dd * Hh,
            Hh, Dd, 0, 0);
    }

    for (int l = 0; l < Ll; l++) {
        const float* xin  = (l == 0)      ? nf  : xg;
        float*       xout = (l == Ll - 1) ? out : xg;

        k_scores<<<ROWS / 8, 256>>>(xin, attn_w + (size_t)l * 2 * Dd);
        k_attn<<<ROWS, 256>>>(adj, attn_b + l);

        // xT (per batch): [Nn, Dd] -> [Dd, Nn] hi/lo
        k_tsplit<<<dim3(Dd / 32, Nn / 32, Bb), tb>>>(
            xin, xthi, xtlo, Nn, Dd, (long long)Nn * Dd, (long long)Dd * Nn);

        // agg = attn @ x   (batched)
        k_mma<0><<<dim3(Dd / 128, Nn / 128, Bb), 256, GEMM_SMEM>>>(
            athi, atlo, xthi, xtlo, aggg, nullptr, nullptr, nullptr,
            Dd, Nn, (long long)Nn * Nn, (long long)Dd * Nn, (long long)Nn * Dd);

        // h = LN(x + agg), emit fp32 + bf16 hi/lo
        k_add_ln<true><<<ROWS, 256>>>(xin, aggg, g1 + (size_t)l * Dd, beta1 + (size_t)l * Dd,
                                      hg, hhi, hlo);

        // hidden = gelu(h @ W1 + b1) -> bf16 hi/lo
        k_mma<1><<<dim3(Hh / 128, ROWS / 128, 1), 256, GEMM_SMEM>>>(
            hhi, hlo, w1thi + (size_t)l * Hh * Dd, w1tlo + (size_t)l * Hh * Dd,
            nullptr, hidhi, hidlo, b1 + (size_t)l * Hh,
            Hh, Dd, 0, 0, 0);

        // ff = hidden @ W2 + b2 -> fp32
        k_mma<2><<<dim3(Dd / 128, ROWS / 128, 1), 256, GEMM_SMEM>>>(
            hidhi, hidlo, w2thi + (size_t)l * Dd * Hh, w2tlo + (size_t)l * Dd * Hh,
            ffg, nullptr, nullptr, b2 + (size_t)l * Dd,
            Dd, Hh, 0, 0, 0);

        // x = LN(h + ff)
        k_add_ln<false><<<ROWS, 256>>>(hg, ffg, g2 + (size_t)l * Dd, beta2 + (size_t)l * Dd,
                                       xout, nullptr, nullptr);
    }
}

// round 14
// speedup vs baseline: 3.1755x; 1.0372x over previous
#include <cuda_runtime.h>
#include <cuda_fp16.h>
#include <math.h>

#define Bb 8
#define Nn 1024
#define Dd 512
#define Hh 2048
#define Ll 3
#define ROWS (Bb*Nn)   // 8192

// ---------------- device scratch (static, allocation-free) ----------------
__device__ float g_x[ROWS * Dd];
__device__ float g_h[ROWS * Dd];
__device__ float g_agg[ROWS * Dd];
__device__ float g_ff[ROWS * Dd];
__device__ float g_si[ROWS];
__device__ float g_sj[ROWS];

__device__ __half g_attn_hi[(size_t)Bb * Nn * Nn];
__device__ __half g_attn_lo[(size_t)Bb * Nn * Nn];
__device__ __half g_h_hi[ROWS * Dd];
__device__ __half g_h_lo[ROWS * Dd];
__device__ __half g_xT_hi[(size_t)Bb * Dd * Nn];
__device__ __half g_xT_lo[(size_t)Bb * Dd * Nn];
__device__ __half g_hid_hi[(size_t)ROWS * Hh];
__device__ __half g_hid_lo[(size_t)ROWS * Hh];
__device__ __half g_W1T_hi[(size_t)Ll * Hh * Dd];
__device__ __half g_W1T_lo[(size_t)Ll * Hh * Dd];
__device__ __half g_W2T_hi[(size_t)Ll * Dd * Hh];
__device__ __half g_W2T_lo[(size_t)Ll * Dd * Hh];

// ---------------- helpers ---------------------------------------------------
__device__ __forceinline__ void f16split(float x, __half& h, __half& l)
{
    h = __float2half_rn(x);
    l = __float2half_rn(x - __half2float(h));
}

__device__ __forceinline__ unsigned s2u(const void* p)
{
    unsigned a;
    asm("{ .reg .u64 t; cvta.to.shared.u64 t, %1; cvt.u32.u64 %0, t; }" : "=r"(a) : "l"(p));
    return a;
}

__device__ __forceinline__ void cpasync16(unsigned dst, const void* src)
{
    asm volatile("cp.async.cg.shared.global [%0], [%1], 16;" :: "r"(dst), "l"(src) : "memory");
}

__device__ __forceinline__ void ldsm4(unsigned& r0, unsigned& r1, unsigned& r2, unsigned& r3,
                                      unsigned addr)
{
    asm volatile("ldmatrix.sync.aligned.m8n8.x4.shared.b16 {%0,%1,%2,%3}, [%4];"
                 : "=r"(r0), "=r"(r1), "=r"(r2), "=r"(r3) : "r"(addr));
}

// hi*hi main term: fp16 inputs, fp32 accumulator
__device__ __forceinline__ void mma_f32(float* d, const unsigned* a, const unsigned* b)
{
    asm volatile("mma.sync.aligned.m16n8k16.row.col.f32.f16.f16.f32 "
                 "{%0,%1,%2,%3}, {%4,%5,%6,%7}, {%8,%9}, {%0,%1,%2,%3};"
                 : "+f"(d[0]), "+f"(d[1]), "+f"(d[2]), "+f"(d[3])
                 : "r"(a[0]), "r"(a[1]), "r"(a[2]), "r"(a[3]), "r"(b[0]), "r"(b[1]));
}

// cross terms: fp16 inputs, fp16 accumulator (potential 2x-rate path)
__device__ __forceinline__ void mma_f16(unsigned* d, const unsigned* a, const unsigned* b)
{
    asm volatile("mma.sync.aligned.m16n8k16.row.col.f16.f16.f16.f16 "
                 "{%0,%1}, {%2,%3,%4,%5}, {%6,%7}, {%0,%1};"
                 : "+r"(d[0]), "+r"(d[1])
                 : "r"(a[0]), "r"(a[1]), "r"(a[2]), "r"(a[3]), "r"(b[0]), "r"(b[1]));
}

// ---------------- kernel 1: per-row attention projections si, sj ----------
__global__ void k_scores(const float* __restrict__ x, const float* __restrict__ aw)
{
    int row  = blockIdx.x * 8 + (threadIdx.x >> 5);
    int lane = threadIdx.x & 31;
    const float* xr = x + (size_t)row * Dd;
    float s1 = 0.f, s2 = 0.f;
    #pragma unroll 4
    for (int k = lane; k < Dd; k += 32) {
        float v = xr[k];
        s1 += v * aw[k];
        s2 += v * aw[Dd + k];
    }
    #pragma unroll
    for (int o = 16; o; o >>= 1) {
        s1 += __shfl_xor_sync(0xffffffffu, s1, o);
        s2 += __shfl_xor_sync(0xffffffffu, s2, o);
    }
    if (lane == 0) { g_si[row] = s1; g_sj[row] = s2; }
}

// ---------------- kernel 2: masked softmax -> fp16 hi/lo (vectorized) ------
__global__ void k_attn(const int* __restrict__ adj, const float* __restrict__ ab_ptr)
{
    const int row = blockIdx.x;
    const int b = row >> 10;
    const int i = row & 1023;
    const int tid = threadIdx.x, lane = tid & 31, wid = tid >> 5;
    const float ab = ab_ptr[0];
    const int jb = tid * 4;

    const int4   a4  = *(const int4*)(adj + (size_t)row * Nn + jb);
    const float4 sj4 = *(const float4*)(g_sj + b * Nn + jb);
    const float si = g_si[row];

    float sc[4];
    {
        const int   av[4] = {a4.x, a4.y, a4.z, a4.w};
        const float sv[4] = {sj4.x, sj4.y, sj4.z, sj4.w};
        #pragma unroll
        for (int q = 0; q < 4; q++) {
            float s = si + sv[q] + ab;
            s = (s >= 0.f) ? s : 0.2f * s;
            bool ok = (av[q] != 0) | ((jb + q) == i);
            sc[q] = ok ? s : -3.4e38f;
        }
    }

    __shared__ float red[8];
    float lmax = fmaxf(fmaxf(sc[0], sc[1]), fmaxf(sc[2], sc[3]));
    #pragma unroll
    for (int o = 16; o; o >>= 1) lmax = fmaxf(lmax, __shfl_xor_sync(0xffffffffu, lmax, o));
    if (lane == 0) red[wid] = lmax;
    __syncthreads();
    float m = red[0];
    #pragma unroll
    for (int w = 1; w < 8; w++) m = fmaxf(m, red[w]);
    __syncthreads();

    float lsum = 0.f;
    #pragma unroll
    for (int q = 0; q < 4; q++) {
        float e = (sc[q] <= -3.0e38f) ? 0.f : expf(sc[q] - m);
        sc[q] = e;
        lsum += e;
    }
    #pragma unroll
    for (int o = 16; o; o >>= 1) lsum += __shfl_xor_sync(0xffffffffu, lsum, o);
    if (lane == 0) red[wid] = lsum;
    __syncthreads();
    float S = 0.f;
    #pragma unroll
    for (int w = 0; w < 8; w++) S += red[w];
    const float inv = 1.f / S;

    unsigned hp[2], lp[2];
    #pragma unroll
    for (int q = 0; q < 4; q += 2) {
        __half h0, l0, h1, l1;
        f16split(sc[q] * inv, h0, l0);
        f16split(sc[q + 1] * inv, h1, l1);
        hp[q >> 1] = (unsigned)__half_as_ushort(h0) |
                     ((unsigned)__half_as_ushort(h1) << 16);
        lp[q >> 1] = (unsigned)__half_as_ushort(l0) |
                     ((unsigned)__half_as_ushort(l1) << 16);
    }
    *(uint2*)(g_attn_hi + (size_t)row * Nn + jb) = make_uint2(hp[0], hp[1]);
    *(uint2*)(g_attn_lo + (size_t)row * Nn + jb) = make_uint2(lp[0], lp[1]);
}

// ---------------- transpose + fp16-split: src[R,C] -> dst[C,R] hi/lo -------
__global__ void k_tsplit(const float* __restrict__ src,
                         __half* __restrict__ dhi,
                         __half* __restrict__ dlo,
                         int R, int C, long long sSrc, long long sDst)
{
    __shared__ float t[32][33];
    const int z = blockIdx.z;
    src += (size_t)z * sSrc;
    const int c0 = blockIdx.x * 32, r0 = blockIdx.y * 32;
    #pragma unroll
    for (int i = threadIdx.y; i < 32; i += 8)
        t[i][threadIdx.x] = src[(size_t)(r0 + i) * C + c0 + threadIdx.x];
    __syncthreads();
    const size_t dbase = (size_t)z * sDst;
    #pragma unroll
    for (int i = threadIdx.y; i < 32; i += 8) {
        float v = t[threadIdx.x][i];
        __half h, l; f16split(v, h, l);
        size_t o = dbase + (size_t)(c0 + i) * R + r0 + threadIdx.x;
        dhi[o] = h; dlo[o] = l;
    }
}

// ---------------- async smem tile loader (128 rows x 64 f16, swizzled) -----
// row r (0-127), 16B chunk c (0-7): off = r*128 + ((c ^ (r&7)) * 16)
__device__ __forceinline__ void ldtile_async(const __half* __restrict__ src,
                                             int K, int kb, unsigned dst, int tid)
{
    #pragma unroll
    for (int it = 0; it < 4; it++) {
        int idx = tid + it * 256;
        int row = idx >> 3, c = idx & 7;
        unsigned off = (unsigned)(row * 128 + ((c ^ (row & 7)) << 4));
        cpasync16(dst + off, src + (size_t)row * K + kb + c * 8);
    }
}

__device__ __forceinline__ void ldstage(const __half* pAH, const __half* pAL,
                                        const __half* pBH, const __half* pBL,
                                        int K, int kb, unsigned buf, int tid)
{
    ldtile_async(pAH, K, kb, buf,         tid);
    ldtile_async(pAL, K, kb, buf + 16384, tid);
    ldtile_async(pBH, K, kb, buf + 32768, tid);
    ldtile_async(pBL, K, kb, buf + 49152, tid);
    asm volatile("cp.async.commit_group;" ::: "memory");
}

// fragment load for one k16 step (chunk pair ch*2 + kc)
__device__ __forceinline__ void ldfrag(unsigned base, int ch, int kc,
                                       const int* rA, const int* rB,
                                       unsigned aH[4][4], unsigned aL[4][4],
                                       unsigned bH[4][2], unsigned bL[4][2])
{
    #pragma unroll
    for (int mt = 0; mt < 4; mt++) {
        const int r = rA[mt];
        const unsigned off = (unsigned)(r * 128 + (((ch * 2 + kc) ^ (r & 7)) << 4));
        ldsm4(aH[mt][0], aH[mt][1], aH[mt][2], aH[mt][3], base + off);
        ldsm4(aL[mt][0], aL[mt][1], aL[mt][2], aL[mt][3], base + 16384 + off);
    }
    #pragma unroll
    for (int ntp = 0; ntp < 2; ntp++) {
        const int r = rB[ntp];
        const unsigned off = (unsigned)(r * 128 + (((ch * 2 + kc) ^ (r & 7)) << 4));
        unsigned q0, q1, q2, q3;
        ldsm4(q0, q1, q2, q3, base + 32768 + off);
        bH[ntp * 2 + 0][0] = q0; bH[ntp * 2 + 0][1] = q2;
        bH[ntp * 2 + 1][0] = q1; bH[ntp * 2 + 1][1] = q3;
        ldsm4(q0, q1, q2, q3, base + 49152 + off);
        bL[ntp * 2 + 0][0] = q0; bL[ntp * 2 + 0][1] = q2;
        bL[ntp * 2 + 1][0] = q1; bL[ntp * 2 + 1][1] = q3;
    }
}

// ---------------- mma.sync fp16x3-split GEMM (f16-acc cross terms) ---------
// C[m,n] = sum_k A[m,k]*B[n,k]; A=[M,K] hi/lo row-major, B=[N,K] hi/lo row-major.
// Main term hi*hi in fp32 acc; cross terms hi*lo + lo*hi share one fp16 acc.
// EPI: 0 = fp32 store, 1 = bias + gelu -> f16 hi/lo, 2 = bias -> fp32.
static constexpr int STAGE_BYTES = 65536;          // 4 x 16KB (Ahi,Alo,Bhi,Blo)
static constexpr int GEMM_SMEM   = 3 * STAGE_BYTES;  // 192 KB, occ 1

template <int EPI>
__global__ void __launch_bounds__(256, 1)
k_mma(const __half* __restrict__ Ahi, const __half* __restrict__ Alo,
      const __half* __restrict__ Bhi, const __half* __restrict__ Blo,
      float* __restrict__ C, __half* __restrict__ Ohi, __half* __restrict__ Olo,
      const float* __restrict__ bias, int Ncols, int K,
      long long sA, long long sB, long long sC)
{
    extern __shared__ char smem[];
    const unsigned sb = s2u(smem);
    const int tid = threadIdx.x, wid = tid >> 5, lane = tid & 31;
    const int z = blockIdx.z;
    const int wm = wid & 1, wn = wid >> 1;     // warp grid 2 (m) x 4 (n)

    const __half* pAH = Ahi + (size_t)z * sA + (size_t)blockIdx.y * 128 * K;
    const __half* pAL = Alo + (size_t)z * sA + (size_t)blockIdx.y * 128 * K;
    const __half* pBH = Bhi + (size_t)z * sB + (size_t)blockIdx.x * 128 * K;
    const __half* pBL = Blo + (size_t)z * sB + (size_t)blockIdx.x * 128 * K;

    float acc[4][4][4];
    unsigned accc[4][4][2];    // fp16x2 cross-term accumulators
    #pragma unroll
    for (int a = 0; a < 4; a++)
        #pragma unroll
        for (int b = 0; b < 4; b++) {
            #pragma unroll
            for (int c = 0; c < 4; c++) acc[a][b][c] = 0.f;
            accc[a][b][0] = 0u; accc[a][b][1] = 0u;
        }

    // per-lane ldmatrix row indices (within 128-row tile)
    int rA[4], rB[2];
    {
        const int lr = (lane & 7) + ((lane >> 3) & 1) * 8;
        #pragma unroll
        for (int mt = 0; mt < 4; mt++) rA[mt] = wm * 64 + mt * 16 + lr;
        #pragma unroll
        for (int ntp = 0; ntp < 2; ntp++) rB[ntp] = wn * 32 + ntp * 16 + lr;
    }
    const int kc = lane >> 4;    // 0/1: k-half chunk within a k16 block

    const int NS = K >> 6;

    // double-buffered fragments
    unsigned aH[2][4][4], aL[2][4][4], bH[2][4][2], bL[2][4][2];

    // prologue: stages 0,1 in flight
    ldstage(pAH, pAL, pBH, pBL, K, 0, sb, tid);
    if (NS > 1) ldstage(pAH, pAL, pBH, pBL, K, 64, sb + STAGE_BYTES, tid);

    for (int s = 0; s < NS; s++) {
        if (s > 0) __syncthreads();        // all warps done reading stage s-1
        if (s + 2 < NS)
            ldstage(pAH, pAL, pBH, pBL, K, (s + 2) << 6,
                    sb + ((s + 2) % 3) * STAGE_BYTES, tid);
        if (s + 2 < NS) {
            asm volatile("cp.async.wait_group 2;" ::: "memory");
        } else if (s + 1 < NS) {
            asm volatile("cp.async.wait_group 1;" ::: "memory");
        } else {
            asm volatile("cp.async.wait_group 0;" ::: "memory");
        }
        __syncthreads();                   // stage s visible CTA-wide

        const unsigned base = sb + (s % 3) * STAGE_BYTES;
        ldfrag(base, 0, kc, rA, rB, aH[0], aL[0], bH[0], bL[0]);
        #pragma unroll
        for (int ks = 0; ks < 4; ks++) {
            const int cur = ks & 1;
            if (ks < 3)
                ldfrag(base, ks + 1, kc, rA, rB,
                       aH[cur ^ 1], aL[cur ^ 1], bH[cur ^ 1], bL[cur ^ 1]);
            #pragma unroll
            for (int mt = 0; mt < 4; mt++)
                #pragma unroll
                for (int nt = 0; nt < 4; nt++) {
                    mma_f32(acc[mt][nt], aH[cur][mt], bH[cur][nt]);
                    mma_f16(accc[mt][nt], aH[cur][mt], bL[cur][nt]);
                    mma_f16(accc[mt][nt], aL[cur][mt], bH[cur][nt]);
                }
        }
    }

    // ---------------- epilogue ----------------
    const int mBase = blockIdx.y * 128 + wm * 64;
    const int nBase = blockIdx.x * 128 + wn * 32;
    #pragma unroll
    for (int mt = 0; mt < 4; mt++)
        #pragma unroll
        for (int half = 0; half < 2; half++) {
            const int m = mBase + mt * 16 + (lane >> 2) + half * 8;
            #pragma unroll
            for (int nt = 0; nt < 4; nt++) {
                const int col = nBase + nt * 8 + (lane & 3) * 2;
                const __half2 cc = *(__half2*)&accc[mt][nt][half];
                float v0 = acc[mt][nt][half * 2 + 0] + __low2float(cc);
                float v1 = acc[mt][nt][half * 2 + 1] + __high2float(cc);
                if (EPI == 0) {
                    float2 v = make_float2(v0, v1);
                    *(float2*)(C + (size_t)z * sC + (size_t)m * Ncols + col) = v;
                } else if (EPI == 2) {
                    float2 v = make_float2(v0 + bias[col], v1 + bias[col + 1]);
                    *(float2*)(C + (size_t)z * sC + (size_t)m * Ncols + col) = v;
                } else {
                    float t0 = v0 + bias[col];
                    float t1 = v1 + bias[col + 1];
                    t0 = 0.5f * t0 * (1.f + erff(t0 * 0.70710678118654752f));
                    t1 = 0.5f * t1 * (1.f + erff(t1 * 0.70710678118654752f));
                    __half h0, l0, h1, l1;
                    f16split(t0, h0, l0);
                    f16split(t1, h1, l1);
                    unsigned hp = (unsigned)__half_as_ushort(h0) |
                                  ((unsigned)__half_as_ushort(h1) << 16);
                    unsigned lp = (unsigned)__half_as_ushort(l0) |
                                  ((unsigned)__half_as_ushort(l1) << 16);
                    *(unsigned*)(Ohi + (size_t)m * Ncols + col) = hp;
                    *(unsigned*)(Olo + (size_t)m * Ncols + col) = lp;
                }
            }
        }
}

// ---------------- residual + LayerNorm (float2, one-pass stats) ------------
template <bool SPLIT>
__global__ void k_add_ln(const float* __restrict__ a, const float* __restrict__ bvec,
                         const float* __restrict__ g, const float* __restrict__ beta,
                         float* __restrict__ out,
                         __half* __restrict__ ohi, __half* __restrict__ olo)
{
    const int row = blockIdx.x;
    const int tid = threadIdx.x, lane = tid & 31, wid = tid >> 5;
    const size_t base = (size_t)row * Dd + tid * 2;

    const float2 a2 = *(const float2*)(a + base);
    const float2 b2 = *(const float2*)(bvec + base);
    const float x0 = a2.x + b2.x, x1 = a2.y + b2.y;

    float s = x0 + x1;
    float q = x0 * x0 + x1 * x1;
    #pragma unroll
    for (int o = 16; o; o >>= 1) {
        s += __shfl_xor_sync(0xffffffffu, s, o);
        q += __shfl_xor_sync(0xffffffffu, q, o);
    }
    __shared__ float ss[8], sq[8];
    if (lane == 0) { ss[wid] = s; sq[wid] = q; }
    __syncthreads();
    float S = 0.f, Q = 0.f;
    #pragma unroll
    for (int w = 0; w < 8; w++) { S += ss[w]; Q += sq[w]; }

    const float mu = S * (1.f / Dd);
    const float var = Q * (1.f / Dd) - mu * mu;
    const float rstd = rsqrtf(var + 1e-5f);

    const float2 gv = *(const float2*)(g + tid * 2);
    const float2 bv = *(const float2*)(beta + tid * 2);
    const float y0 = (x0 - mu) * rstd * gv.x + bv.x;
    const float y1 = (x1 - mu) * rstd * gv.y + bv.y;
    *(float2*)(out + base) = make_float2(y0, y1);

    if (SPLIT) {
        __half h0, l0, h1, l1;
        f16split(y0, h0, l0);
        f16split(y1, h1, l1);
        unsigned hp = (unsigned)__half_as_ushort(h0) |
                      ((unsigned)__half_as_ushort(h1) << 16);
        unsigned lp = (unsigned)__half_as_ushort(l0) |
                      ((unsigned)__half_as_ushort(l1) << 16);
        *(unsigned*)(ohi + base) = hp;
        *(unsigned*)(olo + base) = lp;
    }
}

// ---------------- host launcher --------------------------------------------
extern "C" void kernel_launch(void* const* d_in, const int* in_sizes, int n_in,
                              void* d_out, int out_size)
{
    const float* nf     = (const float*)d_in[0];
    const int*   adj    = (const int*)  d_in[1];
    const float* attn_w = (const float*)d_in[2];
    const float* attn_b = (const float*)d_in[3];
    const float* W1     = (const float*)d_in[4];
    const float* b1     = (const float*)d_in[5];
    const float* W2     = (const float*)d_in[6];
    const float* b2     = (const float*)d_in[7];
    const float* g1     = (const float*)d_in[8];
    const float* beta1  = (const float*)d_in[9];
    const float* g2     = (const float*)d_in[10];
    const float* beta2  = (const float*)d_in[11];
    float* out = (float*)d_out;

    float *xg, *hg, *aggg, *ffg;
    __half *athi, *atlo, *hhi, *hlo, *xthi, *xtlo, *hidhi, *hidlo;
    __half *w1thi, *w1tlo, *w2thi, *w2tlo;
    cudaGetSymbolAddress((void**)&xg,    g_x);
    cudaGetSymbolAddress((void**)&hg,    g_h);
    cudaGetSymbolAddress((void**)&aggg,  g_agg);
    cudaGetSymbolAddress((void**)&ffg,   g_ff);
    cudaGetSymbolAddress((void**)&athi,  g_attn_hi);
    cudaGetSymbolAddress((void**)&atlo,  g_attn_lo);
    cudaGetSymbolAddress((void**)&hhi,   g_h_hi);
    cudaGetSymbolAddress((void**)&hlo,   g_h_lo);
    cudaGetSymbolAddress((void**)&xthi,  g_xT_hi);
    cudaGetSymbolAddress((void**)&xtlo,  g_xT_lo);
    cudaGetSymbolAddress((void**)&hidhi, g_hid_hi);
    cudaGetSymbolAddress((void**)&hidlo, g_hid_lo);
    cudaGetSymbolAddress((void**)&w1thi, g_W1T_hi);
    cudaGetSymbolAddress((void**)&w1tlo, g_W1T_lo);
    cudaGetSymbolAddress((void**)&w2thi, g_W2T_hi);
    cudaGetSymbolAddress((void**)&w2tlo, g_W2T_lo);

    cudaFuncSetAttribute(k_mma<0>, cudaFuncAttributeMaxDynamicSharedMemorySize, GEMM_SMEM);
    cudaFuncSetAttribute(k_mma<1>, cudaFuncAttributeMaxDynamicSharedMemorySize, GEMM_SMEM);
    cudaFuncSetAttribute(k_mma<2>, cudaFuncAttributeMaxDynamicSharedMemorySize, GEMM_SMEM);

    const dim3 tb(32, 8);

    // weight transposes + fp16 split
    for (int l = 0; l < Ll; l++) {
        k_tsplit<<<dim3(Hh / 32, Dd / 32, 1), tb>>>(
            W1 + (size_t)l * Dd * Hh, w1thi + (size_t)l * Hh * Dd, w1tlo + (size_t)l * Hh * Dd,
            Dd, Hh, 0, 0);
        k_tsplit<<<dim3(Dd / 32, Hh / 32, 1), tb>>>(
            W2 + (size_t)l * Hh * Dd, w2thi + (size_t)l * Dd * Hh, w2tlo + (size_t)l * Dd * Hh,
            Hh, Dd, 0, 0);
    }

    for (int l = 0; l < Ll; l++) {
        const float* xin  = (l == 0)      ? nf  : xg;
        float*       xout = (l == Ll - 1) ? out : xg;

        k_scores<<<ROWS / 8, 256>>>(xin, attn_w + (size_t)l * 2 * Dd);
        k_attn<<<ROWS, 256>>>(adj, attn_b + l);

        // xT (per batch): [Nn, Dd] -> [Dd, Nn] hi/lo
        k_tsplit<<<dim3(Dd / 32, Nn / 32, Bb), tb>>>(
            xin, xthi, xtlo, Nn, Dd, (long long)Nn * Dd, (long long)Dd * Nn);

        // agg = attn @ x   (batched)
        k_mma<0><<<dim3(Dd / 128, Nn / 128, Bb), 256, GEMM_SMEM>>>(
            athi, atlo, xthi, xtlo, aggg, nullptr, nullptr, nullptr,
            Dd, Nn, (long long)Nn * Nn, (long long)Dd * Nn, (long long)Nn * Dd);

        // h = LN(x + agg), emit fp32 + f16 hi/lo
        k_add_ln<true><<<ROWS, 256>>>(xin, aggg, g1 + (size_t)l * Dd, beta1 + (size_t)l * Dd,
                                      hg, hhi, hlo);

        // hidden = gelu(h @ W1 + b1) -> f16 hi/lo
        k_mma<1><<<dim3(Hh / 128, ROWS / 128, 1), 256, GEMM_SMEM>>>(
            hhi, hlo, w1thi + (size_t)l * Hh * Dd, w1tlo + (size_t)l * Hh * Dd,
            nullptr, hidhi, hidlo, b1 + (size_t)l * Hh,
            Hh, Dd, 0, 0, 0);

        // ff = hidden @ W2 + b2 -> fp32
        k_mma<2><<<dim3(Dd / 128, ROWS / 128, 1), 256, GEMM_SMEM>>>(
            hidhi, hidlo, w2thi + (size_t)l * Dd * Hh, w2tlo + (size_t)l * Dd * Hh,
            ffg, nullptr, nullptr, b2 + (size_t)l * Dd,
            Dd, Hh, 0, 0, 0);

        // x = LN(h + ff)
        k_add_ln<false><<<ROWS, 256>>>(hg, ffg, g2 + (size_t)l * Dd, beta2 + (size_t)l * Dd,
                                       xout, nullptr, nullptr);
    }
}

// round 15
// speedup vs baseline: 3.6901x; 1.1621x over previous
#include <cuda_runtime.h>
#include <cuda_fp16.h>
#include <math.h>

#define Bb 8
#define Nn 1024
#define Dd 512
#define Hh 2048
#define Ll 3
#define ROWS (Bb*Nn)   // 8192

// ---------------- device scratch (static, allocation-free) ----------------
__device__ float g_x[ROWS * Dd];
__device__ float g_h[ROWS * Dd];
__device__ float g_agg[ROWS * Dd];
__device__ float g_ff[ROWS * Dd];
__device__ float g_si[ROWS];
__device__ float g_sj[ROWS];

__device__ __half g_attn_hi[(size_t)Bb * Nn * Nn];
__device__ __half g_attn_lo[(size_t)Bb * Nn * Nn];
__device__ __half g_h_hi[ROWS * Dd];
__device__ __half g_h_lo[ROWS * Dd];
__device__ __half g_x_hi[ROWS * Dd];          // row-major splits of x (B operand of agg)
__device__ __half g_x_lo[ROWS * Dd];
__device__ __half g_hid_hi[(size_t)ROWS * Hh];
__device__ __half g_hid_lo[(size_t)ROWS * Hh];
__device__ __half g_W1s_hi[(size_t)Ll * Dd * Hh];   // same layout as W1 [d][4d]
__device__ __half g_W1s_lo[(size_t)Ll * Dd * Hh];
__device__ __half g_W2s_hi[(size_t)Ll * Hh * Dd];   // same layout as W2 [4d][d]
__device__ __half g_W2s_lo[(size_t)Ll * Hh * Dd];

// ---------------- helpers ---------------------------------------------------
__device__ __forceinline__ void f16split(float x, __half& h, __half& l)
{
    h = __float2half_rn(x);
    l = __float2half_rn(x - __half2float(h));
}

__device__ __forceinline__ unsigned packh(__half a, __half b)
{
    return (unsigned)__half_as_ushort(a) | ((unsigned)__half_as_ushort(b) << 16);
}

__device__ __forceinline__ unsigned s2u(const void* p)
{
    unsigned a;
    asm("{ .reg .u64 t; cvta.to.shared.u64 t, %1; cvt.u32.u64 %0, t; }" : "=r"(a) : "l"(p));
    return a;
}

__device__ __forceinline__ void cpasync16(unsigned dst, const void* src)
{
    asm volatile("cp.async.cg.shared.global [%0], [%1], 16;" :: "r"(dst), "l"(src) : "memory");
}

__device__ __forceinline__ void ldsm4(unsigned& r0, unsigned& r1, unsigned& r2, unsigned& r3,
                                      unsigned addr)
{
    asm volatile("ldmatrix.sync.aligned.m8n8.x4.shared.b16 {%0,%1,%2,%3}, [%4];"
                 : "=r"(r0), "=r"(r1), "=r"(r2), "=r"(r3) : "r"(addr));
}

__device__ __forceinline__ void ldsm4t(unsigned& r0, unsigned& r1, unsigned& r2, unsigned& r3,
                                       unsigned addr)
{
    asm volatile("ldmatrix.sync.aligned.m8n8.x4.trans.shared.b16 {%0,%1,%2,%3}, [%4];"
                 : "=r"(r0), "=r"(r1), "=r"(r2), "=r"(r3) : "r"(addr));
}

// hi*hi main term: fp16 inputs, fp32 accumulator
__device__ __forceinline__ void mma_f32(float* d, const unsigned* a, const unsigned* b)
{
    asm volatile("mma.sync.aligned.m16n8k16.row.col.f32.f16.f16.f32 "
                 "{%0,%1,%2,%3}, {%4,%5,%6,%7}, {%8,%9}, {%0,%1,%2,%3};"
                 : "+f"(d[0]), "+f"(d[1]), "+f"(d[2]), "+f"(d[3])
                 : "r"(a[0]), "r"(a[1]), "r"(a[2]), "r"(a[3]), "r"(b[0]), "r"(b[1]));
}

// cross terms: fp16 accumulator
__device__ __forceinline__ void mma_f16(unsigned* d, const unsigned* a, const unsigned* b)
{
    asm volatile("mma.sync.aligned.m16n8k16.row.col.f16.f16.f16.f16 "
                 "{%0,%1}, {%2,%3,%4,%5}, {%6,%7}, {%0,%1};"
                 : "+r"(d[0]), "+r"(d[1])
                 : "r"(a[0]), "r"(a[1]), "r"(a[2]), "r"(a[3]), "r"(b[0]), "r"(b[1]));
}

// ---------------- weight split: elementwise fp32 -> f16 hi/lo --------------
__global__ void k_wsplit(const float* __restrict__ src,
                         __half* __restrict__ dhi, __half* __restrict__ dlo, int n4)
{
    int i = blockIdx.x * 256 + threadIdx.x;
    if (i >= n4) return;
    float4 v = ((const float4*)src)[i];
    __half h0, l0, h1, l1, h2, l2, h3, l3;
    f16split(v.x, h0, l0); f16split(v.y, h1, l1);
    f16split(v.z, h2, l2); f16split(v.w, h3, l3);
    ((uint2*)dhi)[i] = make_uint2(packh(h0, h1), packh(h2, h3));
    ((uint2*)dlo)[i] = make_uint2(packh(l0, l1), packh(l2, l3));
}

// ---------------- layer-0: split nf -> x hi/lo + scores (attn_w[0]) --------
__global__ void k_split_scores(const float* __restrict__ x, const float* __restrict__ aw)
{
    const int row = blockIdx.x;
    const int tid = threadIdx.x, lane = tid & 31, wid = tid >> 5;
    const size_t base = (size_t)row * Dd + tid * 2;

    const float2 v = *(const float2*)(x + base);
    __half h0, l0, h1, l1;
    f16split(v.x, h0, l0); f16split(v.y, h1, l1);
    *(unsigned*)(g_x_hi + base) = packh(h0, h1);
    *(unsigned*)(g_x_lo + base) = packh(l0, l1);

    const float2 w1 = *(const float2*)(aw + tid * 2);
    const float2 w2 = *(const float2*)(aw + Dd + tid * 2);
    float s1 = v.x * w1.x + v.y * w1.y;
    float s2 = v.x * w2.x + v.y * w2.y;
    #pragma unroll
    for (int o = 16; o; o >>= 1) {
        s1 += __shfl_xor_sync(0xffffffffu, s1, o);
        s2 += __shfl_xor_sync(0xffffffffu, s2, o);
    }
    __shared__ float r1[8], r2[8];
    if (lane == 0) { r1[wid] = s1; r2[wid] = s2; }
    __syncthreads();
    if (tid == 0) {
        float a = 0.f, b = 0.f;
        #pragma unroll
        for (int w = 0; w < 8; w++) { a += r1[w]; b += r2[w]; }
        g_si[row] = a; g_sj[row] = b;
    }
}

// ---------------- masked softmax -> fp16 hi/lo (vectorized) ----------------
__global__ void k_attn(const int* __restrict__ adj, const float* __restrict__ ab_ptr)
{
    const int row = blockIdx.x;
    const int b = row >> 10;
    const int i = row & 1023;
    const int tid = threadIdx.x, lane = tid & 31, wid = tid >> 5;
    const float ab = ab_ptr[0];
    const int jb = tid * 4;

    const int4   a4  = *(const int4*)(adj + (size_t)row * Nn + jb);
    const float4 sj4 = *(const float4*)(g_sj + b * Nn + jb);
    const float si = g_si[row];

    float sc[4];
    {
        const int   av[4] = {a4.x, a4.y, a4.z, a4.w};
        const float sv[4] = {sj4.x, sj4.y, sj4.z, sj4.w};
        #pragma unroll
        for (int q = 0; q < 4; q++) {
            float s = si + sv[q] + ab;
            s = (s >= 0.f) ? s : 0.2f * s;
            bool ok = (av[q] != 0) | ((jb + q) == i);
            sc[q] = ok ? s : -3.4e38f;
        }
    }

    __shared__ float red[8];
    float lmax = fmaxf(fmaxf(sc[0], sc[1]), fmaxf(sc[2], sc[3]));
    #pragma unroll
    for (int o = 16; o; o >>= 1) lmax = fmaxf(lmax, __shfl_xor_sync(0xffffffffu, lmax, o));
    if (lane == 0) red[wid] = lmax;
    __syncthreads();
    float m = red[0];
    #pragma unroll
    for (int w = 1; w < 8; w++) m = fmaxf(m, red[w]);
    __syncthreads();

    float lsum = 0.f;
    #pragma unroll
    for (int q = 0; q < 4; q++) {
        float e = (sc[q] <= -3.0e38f) ? 0.f : expf(sc[q] - m);
        sc[q] = e;
        lsum += e;
    }
    #pragma unroll
    for (int o = 16; o; o >>= 1) lsum += __shfl_xor_sync(0xffffffffu, lsum, o);
    if (lane == 0) red[wid] = lsum;
    __syncthreads();
    float S = 0.f;
    #pragma unroll
    for (int w = 0; w < 8; w++) S += red[w];
    const float inv = 1.f / S;

    unsigned hp[2], lp[2];
    #pragma unroll
    for (int q = 0; q < 4; q += 2) {
        __half h0, l0, h1, l1;
        f16split(sc[q] * inv, h0, l0);
        f16split(sc[q + 1] * inv, h1, l1);
        hp[q >> 1] = packh(h0, h1);
        lp[q >> 1] = packh(l0, l1);
    }
    *(uint2*)(g_attn_hi + (size_t)row * Nn + jb) = make_uint2(hp[0], hp[1]);
    *(uint2*)(g_attn_lo + (size_t)row * Nn + jb) = make_uint2(lp[0], lp[1]);
}

// ---------------- smem loaders ---------------------------------------------
// A tile: 128 m-rows x 64 k (row-major, pitch K). chunk c 0-7:
//   off = r*128 + ((c ^ (r&7)) << 4)
__device__ __forceinline__ void ldtileA_async(const __half* __restrict__ src,
                                              int K, int kb, unsigned dst, int tid)
{
    #pragma unroll
    for (int it = 0; it < 4; it++) {
        int idx = tid + it * 256;
        int row = idx >> 3, c = idx & 7;
        unsigned off = (unsigned)(row * 128 + ((c ^ (row & 7)) << 4));
        cpasync16(dst + off, src + (size_t)row * K + kb + c * 8);
    }
}

// B tile: 64 k-rows x 128 n (row-major [k][n], pitch NB). chunk c 0-15:
//   off = r*256 + ((c ^ (r&7)) << 4)
__device__ __forceinline__ void ldtileB_async(const __half* __restrict__ src,
                                              int NB, int kb, unsigned dst, int tid)
{
    #pragma unroll
    for (int it = 0; it < 4; it++) {
        int idx = tid + it * 256;
        int row = idx >> 4, c = idx & 15;
        unsigned off = (unsigned)(row * 256 + ((c ^ (row & 7)) << 4));
        cpasync16(dst + off, src + (size_t)(kb + row) * NB + c * 8);
    }
}

__device__ __forceinline__ void ldstage(const __half* pAH, const __half* pAL,
                                        const __half* pBH, const __half* pBL,
                                        int K, int NB, int kb, unsigned buf, int tid)
{
    ldtileA_async(pAH, K, kb, buf,         tid);
    ldtileA_async(pAL, K, kb, buf + 16384, tid);
    ldtileB_async(pBH, NB, kb, buf + 32768, tid);
    ldtileB_async(pBL, NB, kb, buf + 49152, tid);
    asm volatile("cp.async.commit_group;" ::: "memory");
}

// fragment load for one k16 step
__device__ __forceinline__ void ldfrag(unsigned base, int ks, int kc,
                                       const int* rA, int krbase, int cbase,
                                       unsigned aH[4][4], unsigned aL[4][4],
                                       unsigned bH[4][2], unsigned bL[4][2])
{
    #pragma unroll
    for (int mt = 0; mt < 4; mt++) {
        const int r = rA[mt];
        const unsigned off = (unsigned)(r * 128 + (((ks * 2 + kc) ^ (r & 7)) << 4));
        ldsm4(aH[mt][0], aH[mt][1], aH[mt][2], aH[mt][3], base + off);
        ldsm4(aL[mt][0], aL[mt][1], aL[mt][2], aL[mt][3], base + 16384 + off);
    }
    const int kr = ks * 16 + krbase;
    const unsigned swr = (unsigned)(kr & 7);
    #pragma unroll
    for (int ntp = 0; ntp < 2; ntp++) {
        const unsigned c = (unsigned)(cbase + ntp * 2);
        const unsigned off = (unsigned)(kr * 256) + ((c ^ swr) << 4);
        unsigned q0, q1, q2, q3;
        ldsm4t(q0, q1, q2, q3, base + 32768 + off);
        bH[ntp * 2 + 0][0] = q0; bH[ntp * 2 + 0][1] = q1;
        bH[ntp * 2 + 1][0] = q2; bH[ntp * 2 + 1][1] = q3;
        ldsm4t(q0, q1, q2, q3, base + 49152 + off);
        bL[ntp * 2 + 0][0] = q0; bL[ntp * 2 + 0][1] = q1;
        bL[ntp * 2 + 1][0] = q2; bL[ntp * 2 + 1][1] = q3;
    }
}

// ---------------- mma.sync fp16x3-split GEMM (trans-B, no transposes) ------
// C[m,n] = sum_k A[m,k]*B[k,n]; A=[M,K] hi/lo row-major, B=[K,NB] hi/lo row-major.
// EPI: 0 = fp32 store, 1 = bias + gelu -> f16 hi/lo, 2 = bias -> fp32.
static constexpr int STAGE_BYTES = 65536;
static constexpr int GEMM_SMEM   = 3 * STAGE_BYTES;  // 192 KB, occ 1

template <int EPI>
__global__ void __launch_bounds__(256, 1)
k_mma(const __half* __restrict__ Ahi, const __half* __restrict__ Alo,
      const __half* __restrict__ Bhi, const __half* __restrict__ Blo,
      float* __restrict__ C, __half* __restrict__ Ohi, __half* __restrict__ Olo,
      const float* __restrict__ bias, int Ncols, int NB, int K,
      long long sA, long long sB, long long sC)
{
    extern __shared__ char smem[];
    const unsigned sb = s2u(smem);
    const int tid = threadIdx.x, wid = tid >> 5, lane = tid & 31;
    const int z = blockIdx.z;
    const int wm = wid & 1, wn = wid >> 1;     // warp grid 2 (m) x 4 (n)

    const __half* pAH = Ahi + (size_t)z * sA + (size_t)blockIdx.y * 128 * K;
    const __half* pAL = Alo + (size_t)z * sA + (size_t)blockIdx.y * 128 * K;
    const __half* pBH = Bhi + (size_t)z * sB + (size_t)blockIdx.x * 128;   // column offset
    const __half* pBL = Blo + (size_t)z * sB + (size_t)blockIdx.x * 128;

    float acc[4][4][4];
    unsigned accc[4][4][2];
    #pragma unroll
    for (int a = 0; a < 4; a++)
        #pragma unroll
        for (int b = 0; b < 4; b++) {
            #pragma unroll
            for (int c = 0; c < 4; c++) acc[a][b][c] = 0.f;
            accc[a][b][0] = 0u; accc[a][b][1] = 0u;
        }

    int rA[4];
    {
        const int lr = (lane & 7) + ((lane >> 3) & 1) * 8;
        #pragma unroll
        for (int mt = 0; mt < 4; mt++) rA[mt] = wm * 64 + mt * 16 + lr;
    }
    const int kc = lane >> 4;                         // A: k-half select
    const int krbase = ((lane >> 3) & 1) * 8 + (lane & 7);  // B: k-row within k16
    const int cbase  = wn * 4 + (lane >> 4);                // B: n-chunk base

    const int NS = K >> 6;

    unsigned aH[2][4][4], aL[2][4][4], bH[2][4][2], bL[2][4][2];

    ldstage(pAH, pAL, pBH, pBL, K, NB, 0, sb, tid);
    if (NS > 1) ldstage(pAH, pAL, pBH, pBL, K, NB, 64, sb + STAGE_BYTES, tid);

    for (int s = 0; s < NS; s++) {
        if (s > 0) __syncthreads();
        if (s + 2 < NS)
            ldstage(pAH, pAL, pBH, pBL, K, NB, (s + 2) << 6,
                    sb + ((s + 2) % 3) * STAGE_BYTES, tid);
        if (s + 2 < NS) {
            asm volatile("cp.async.wait_group 2;" ::: "memory");
        } else if (s + 1 < NS) {
            asm volatile("cp.async.wait_group 1;" ::: "memory");
        } else {
            asm volatile("cp.async.wait_group 0;" ::: "memory");
        }
        __syncthreads();

        const unsigned base = sb + (s % 3) * STAGE_BYTES;
        ldfrag(base, 0, kc, rA, krbase, cbase, aH[0], aL[0], bH[0], bL[0]);
        #pragma unroll
        for (int ks = 0; ks < 4; ks++) {
            const int cur = ks & 1;
            if (ks < 3)
                ldfrag(base, ks + 1, kc, rA, krbase, cbase,
                       aH[cur ^ 1], aL[cur ^ 1], bH[cur ^ 1], bL[cur ^ 1]);
            #pragma unroll
            for (int mt = 0; mt < 4; mt++)
                #pragma unroll
                for (int nt = 0; nt < 4; nt++) {
                    mma_f32(acc[mt][nt], aH[cur][mt], bH[cur][nt]);
                    mma_f16(accc[mt][nt], aH[cur][mt], bL[cur][nt]);
                    mma_f16(accc[mt][nt], aL[cur][mt], bH[cur][nt]);
                }
        }
    }

    // ---------------- epilogue ----------------
    const int mBase = blockIdx.y * 128 + wm * 64;
    const int nBase = blockIdx.x * 128 + wn * 32;
    #pragma unroll
    for (int mt = 0; mt < 4; mt++)
        #pragma unroll
        for (int half = 0; half < 2; half++) {
            const int m = mBase + mt * 16 + (lane >> 2) + half * 8;
            #pragma unroll
            for (int nt = 0; nt < 4; nt++) {
                const int col = nBase + nt * 8 + (lane & 3) * 2;
                const __half2 cc = *(__half2*)&accc[mt][nt][half];
                float v0 = acc[mt][nt][half * 2 + 0] + __low2float(cc);
                float v1 = acc[mt][nt][half * 2 + 1] + __high2float(cc);
                if (EPI == 0) {
                    *(float2*)(C + (size_t)z * sC + (size_t)m * Ncols + col) =
                        make_float2(v0, v1);
                } else if (EPI == 2) {
                    *(float2*)(C + (size_t)z * sC + (size_t)m * Ncols + col) =
                        make_float2(v0 + bias[col], v1 + bias[col + 1]);
                } else {
                    float t0 = v0 + bias[col];
                    float t1 = v1 + bias[col + 1];
                    t0 = 0.5f * t0 * (1.f + erff(t0 * 0.70710678118654752f));
                    t1 = 0.5f * t1 * (1.f + erff(t1 * 0.70710678118654752f));
                    __half h0, l0, h1, l1;
                    f16split(t0, h0, l0);
                    f16split(t1, h1, l1);
                    *(unsigned*)(Ohi + (size_t)m * Ncols + col) = packh(h0, h1);
                    *(unsigned*)(Olo + (size_t)m * Ncols + col) = packh(l0, l1);
                }
            }
        }
}

// ---------------- residual + LayerNorm (+splits, +next-layer scores) -------
template <bool SPLIT>
__global__ void k_add_ln(const float* __restrict__ a, const float* __restrict__ bvec,
                         const float* __restrict__ g, const float* __restrict__ beta,
                         float* __restrict__ out,
                         __half* __restrict__ ohi, __half* __restrict__ olo,
                         const float* __restrict__ aw)
{
    const int row = blockIdx.x;
    const int tid = threadIdx.x, lane = tid & 31, wid = tid >> 5;
    const size_t base = (size_t)row * Dd + tid * 2;

    const float2 a2 = *(const float2*)(a + base);
    const float2 b2 = *(const float2*)(bvec + base);
    const float x0 = a2.x + b2.x, x1 = a2.y + b2.y;

    float s = x0 + x1;
    float q = x0 * x0 + x1 * x1;
    #pragma unroll
    for (int o = 16; o; o >>= 1) {
        s += __shfl_xor_sync(0xffffffffu, s, o);
        q += __shfl_xor_sync(0xffffffffu, q, o);
    }
    __shared__ float ss[8], sq[8];
    if (lane == 0) { ss[wid] = s; sq[wid] = q; }
    __syncthreads();
    float S = 0.f, Q = 0.f;
    #pragma unroll
    for (int w = 0; w < 8; w++) { S += ss[w]; Q += sq[w]; }

    const float mu = S * (1.f / Dd);
    const float var = Q * (1.f / Dd) - mu * mu;
    const float rstd = rsqrtf(var + 1e-5f);

    const float2 gv = *(const float2*)(g + tid * 2);
    const float2 bv = *(const float2*)(beta + tid * 2);
    const float y0 = (x0 - mu) * rstd * gv.x + bv.x;
    const float y1 = (x1 - mu) * rstd * gv.y + bv.y;
    *(float2*)(out + base) = make_float2(y0, y1);

    if (SPLIT) {
        __half h0, l0, h1, l1;
        f16split(y0, h0, l0);
        f16split(y1, h1, l1);
        *(unsigned*)(ohi + base) = packh(h0, h1);
        *(unsigned*)(olo + base) = packh(l0, l1);
    }

    if (aw) {   // next-layer attention projections, fused
        const float2 w1 = *(const float2*)(aw + tid * 2);
        const float2 w2 = *(const float2*)(aw + Dd + tid * 2);
        float s1 = y0 * w1.x + y1 * w1.y;
        float s2 = y0 * w2.x + y1 * w2.y;
        #pragma unroll
        for (int o = 16; o; o >>= 1) {
            s1 += __shfl_xor_sync(0xffffffffu, s1, o);
            s2 += __shfl_xor_sync(0xffffffffu, s2, o);
        }
        __syncthreads();   // ss/sq reuse
        if (lane == 0) { ss[wid] = s1; sq[wid] = s2; }
        __syncthreads();
        if (tid == 0) {
            float u = 0.f, v = 0.f;
            #pragma unroll
            for (int w = 0; w < 8; w++) { u += ss[w]; v += sq[w]; }
            g_si[row] = u; g_sj[row] = v;
        }
    }
}

// ---------------- host launcher --------------------------------------------
extern "C" void kernel_launch(void* const* d_in, const int* in_sizes, int n_in,
                              void* d_out, int out_size)
{
    const float* nf     = (const float*)d_in[0];
    const int*   adj    = (const int*)  d_in[1];
    const float* attn_w = (const float*)d_in[2];
    const float* attn_b = (const float*)d_in[3];
    const float* W1     = (const float*)d_in[4];
    const float* b1     = (const float*)d_in[5];
    const float* W2     = (const float*)d_in[6];
    const float* b2     = (const float*)d_in[7];
    const float* g1     = (const float*)d_in[8];
    const float* beta1  = (const float*)d_in[9];
    const float* g2     = (const float*)d_in[10];
    const float* beta2  = (const float*)d_in[11];
    float* out = (float*)d_out;

    float *xg, *hg, *aggg, *ffg;
    __half *athi, *atlo, *hhi, *hlo, *xhi, *xlo, *hidhi, *hidlo;
    __half *w1hi, *w1lo, *w2hi, *w2lo;
    cudaGetSymbolAddress((void**)&xg,    g_x);
    cudaGetSymbolAddress((void**)&hg,    g_h);
    cudaGetSymbolAddress((void**)&aggg,  g_agg);
    cudaGetSymbolAddress((void**)&ffg,   g_ff);
    cudaGetSymbolAddress((void**)&athi,  g_attn_hi);
    cudaGetSymbolAddress((void**)&atlo,  g_attn_lo);
    cudaGetSymbolAddress((void**)&hhi,   g_h_hi);
    cudaGetSymbolAddress((void**)&hlo,   g_h_lo);
    cudaGetSymbolAddress((void**)&xhi,   g_x_hi);
    cudaGetSymbolAddress((void**)&xlo,   g_x_lo);
    cudaGetSymbolAddress((void**)&hidhi, g_hid_hi);
    cudaGetSymbolAddress((void**)&hidlo, g_hid_lo);
    cudaGetSymbolAddress((void**)&w1hi,  g_W1s_hi);
    cudaGetSymbolAddress((void**)&w1lo,  g_W1s_lo);
    cudaGetSymbolAddress((void**)&w2hi,  g_W2s_hi);
    cudaGetSymbolAddress((void**)&w2lo,  g_W2s_lo);

    cudaFuncSetAttribute(k_mma<0>, cudaFuncAttributeMaxDynamicSharedMemorySize, GEMM_SMEM);
    cudaFuncSetAttribute(k_mma<1>, cudaFuncAttributeMaxDynamicSharedMemorySize, GEMM_SMEM);
    cudaFuncSetAttribute(k_mma<2>, cudaFuncAttributeMaxDynamicSharedMemorySize, GEMM_SMEM);

    // weight splits (no transpose — GEMM consumes [K][N] row-major via ldmatrix.trans)
    {
        const int n4 = (Ll * Dd * Hh) / 4;
        k_wsplit<<<(n4 + 255) / 256, 256>>>(W1, w1hi, w1lo, n4);
        k_wsplit<<<(n4 + 255) / 256, 256>>>(W2, w2hi, w2lo, n4);
    }
    // layer-0 x splits + scores
    k_split_scores<<<ROWS, 256>>>(nf, attn_w);

    for (int l = 0; l < Ll; l++) {
        const float* xin = (l == 0) ? nf : xg;

        k_attn<<<ROWS, 256>>>(adj, attn_b + l);

        // agg = attn @ x   (batched; B = row-major x splits)
        k_mma<0><<<dim3(Dd / 128, Nn / 128, Bb), 256, GEMM_SMEM>>>(
            athi, atlo, xhi, xlo, aggg, nullptr, nullptr, nullptr,
            Dd, Dd, Nn, (long long)Nn * Nn, (long long)Nn * Dd, (long long)Nn * Dd);

        // h = LN(x + agg), emit fp32 + f16 hi/lo
        k_add_ln<true><<<ROWS, 256>>>(xin, aggg, g1 + (size_t)l * Dd, beta1 + (size_t)l * Dd,
                                      hg, hhi, hlo, nullptr);

        // hidden = gelu(h @ W1 + b1) -> f16 hi/lo
        k_mma<1><<<dim3(Hh / 128, ROWS / 128, 1), 256, GEMM_SMEM>>>(
            hhi, hlo, w1hi + (size_t)l * Dd * Hh, w1lo + (size_t)l * Dd * Hh,
            nullptr, hidhi, hidlo, b1 + (size_t)l * Hh,
            Hh, Hh, Dd, 0, 0, 0);

        // ff = hidden @ W2 + b2 -> fp32
        k_mma<2><<<dim3(Dd / 128, ROWS / 128, 1), 256, GEMM_SMEM>>>(
            hidhi, hidlo, w2hi + (size_t)l * Hh * Dd, w2lo + (size_t)l * Hh * Dd,
            ffg, nullptr, nullptr, b2 + (size_t)l * Dd,
            Dd, Dd, Hh, 0, 0, 0);

        // x = LN(h + ff); for l < L-1 also emit x splits + next-layer scores
        if (l < Ll - 1) {
            k_add_ln<true><<<ROWS, 256>>>(hg, ffg, g2 + (size_t)l * Dd, beta2 + (size_t)l * Dd,
                                          xg, xhi, xlo, attn_w + (size_t)(l + 1) * 2 * Dd);
        } else {
            k_add_ln<false><<<ROWS, 256>>>(hg, ffg, g2 + (size_t)l * Dd, beta2 + (size_t)l * Dd,
                                           out, nullptr, nullptr, nullptr);
        }
    }
}